// round 8
// baseline (speedup 1.0000x reference)
#include <cuda_runtime.h>
#include <cstdint>

#define D_MODEL 1024
#define NUM_HEADS 16
#define D_K 64
#define BATCH 4
#define SEQ 2048
#define BH (BATCH * NUM_HEADS)          // 64
#define M_ROWS (BATCH * SEQ)            // 8192

// Scratch (device globals; no dynamic allocation allowed)
__device__ float g_q[(size_t)BH * SEQ * D_K];
__device__ float g_k[(size_t)BH * SEQ * D_K];
__device__ float g_vt[(size_t)BH * D_K * SEQ];   // V transposed: [bh][d][s]
__device__ float g_ctx[(size_t)M_ROWS * D_MODEL];
__device__ float g_l[(size_t)BH * SEQ];          // INVERSE softmax row sums
__device__ float g_attn_fb[(size_t)BH * SEQ * SEQ];

// Round fp32 -> tf32 (round-to-nearest; HMMA then truncates losslessly)
__device__ __forceinline__ uint32_t rn_tf32(float x) {
    return (__float_as_uint(x) + 0x1000u) & 0xFFFFE000u;
}

__device__ __forceinline__ void mma_tf32(float* d, const uint32_t* a, const uint32_t* b) {
    asm volatile(
        "mma.sync.aligned.m16n8k8.row.col.f32.tf32.tf32.f32 "
        "{%0,%1,%2,%3}, {%4,%5,%6,%7}, {%8,%9}, {%0,%1,%2,%3};"
        : "+f"(d[0]), "+f"(d[1]), "+f"(d[2]), "+f"(d[3])
        : "r"(a[0]), "r"(a[1]), "r"(a[2]), "r"(a[3]), "r"(b[0]), "r"(b[1]));
}

// Fragment smem block strides (padded to break STS bank conflicts)
#define ABLK 132   // 128 floats + 4 pad
#define BBLK 66    // 64 floats + 2 pad

// ---------------------------------------------------------------------------
// Projection GEMM:  C = A(M x K, K-major) * B(N x K, K-major)^T   (tf32 MMA)
// Block tile 128 x 128, BK = 32, 256 threads, warps 4x2, 2 CTAs/SM.
// EPI: 0 = split-heads Q/K (+bias), 1 = V transposed (+bias), 2 = row-major (+bias)
// ---------------------------------------------------------------------------
template <int EPI>
__global__ void __launch_bounds__(256, 2) mma_gemm(
    const float* __restrict__ A, const float* __restrict__ B,
    const float* __restrict__ bias, float* __restrict__ C,
    int K, int lda, int ldb)
{
    constexpr int A_FLOATS = 32 * ABLK;
    constexpr int B_FLOATS = 64 * BBLK;

    extern __shared__ float smf[];
    float* As = smf;
    float* Bs = smf + 2 * A_FLOATS;

    const int tid = threadIdx.x;
    const int wid = tid >> 5, lid = tid & 31;
    const int warp_m = wid >> 1, warp_n = wid & 1;
    const int bm = blockIdx.y * 128;
    const int bn = blockIdx.x * 128;

    const float* Ab = A + (size_t)bm * lda;
    const float* Bb = B + (size_t)bn * ldb;

    float4 ra[4], rb[4];

    auto ldg_tiles = [&](int k0) {
#pragma unroll
        for (int it = 0; it < 4; it++) {
            int f = tid + it * 256;
            int row = f >> 3, k4 = f & 7;
            ra[it] = *(const float4*)(Ab + (size_t)row * lda + k0 + k4 * 4);
            rb[it] = *(const float4*)(Bb + (size_t)row * ldb + k0 + k4 * 4);
        }
    };

    auto sts_tiles = [&](int buf) {
        float* da = As + buf * A_FLOATS;
        float* db = Bs + buf * B_FLOATS;
#pragma unroll
        for (int it = 0; it < 4; it++) {
            int f = tid + it * 256;
            int row = f >> 3, k4 = f & 7;
            {
                int ma = row >> 4, r = row & 15;
                int ka = k4 >> 1;
                int slot = ((k4 & 1) << 1) | (r >> 3);
                float* p = da + ((ka * 8 + ma) * ABLK + ((r & 7) << 4) + slot);
                p[0]  = __uint_as_float(rn_tf32(ra[it].x));
                p[4]  = __uint_as_float(rn_tf32(ra[it].y));
                p[8]  = __uint_as_float(rn_tf32(ra[it].z));
                p[12] = __uint_as_float(rn_tf32(ra[it].w));
            }
            {
                int na = row >> 3, nn = row & 7;
                int ka = k4 >> 1;
                int slot = k4 & 1;
                float* p = db + ((ka * 16 + na) * BBLK + (nn << 3) + slot);
                p[0] = __uint_as_float(rn_tf32(rb[it].x));
                p[2] = __uint_as_float(rn_tf32(rb[it].y));
                p[4] = __uint_as_float(rn_tf32(rb[it].z));
                p[6] = __uint_as_float(rn_tf32(rb[it].w));
            }
        }
    };

    float acc[2][8][4];
#pragma unroll
    for (int im = 0; im < 2; im++)
#pragma unroll
        for (int in = 0; in < 8; in++)
#pragma unroll
            for (int c = 0; c < 4; c++) acc[im][in][c] = 0.f;

    const int KS = K >> 5;
    ldg_tiles(0);
    sts_tiles(0);
    ldg_tiles(32);
    __syncthreads();

    for (int ks = 0; ks < KS; ks++) {
        if (ks + 1 < KS) sts_tiles((ks + 1) & 1);
        if (ks + 2 < KS) ldg_tiles((ks + 2) << 5);

        const float* Ad = As + (ks & 1) * A_FLOATS;
        const float* Bd = Bs + (ks & 1) * B_FLOATS;
#pragma unroll
        for (int ka = 0; ka < 4; ka++) {
            uint32_t afr[2][4];
#pragma unroll
            for (int im = 0; im < 2; im++) {
                const float4 v = *(const float4*)(Ad + (ka * 8 + warp_m * 2 + im) * ABLK + lid * 4);
                afr[im][0] = __float_as_uint(v.x); afr[im][1] = __float_as_uint(v.y);
                afr[im][2] = __float_as_uint(v.z); afr[im][3] = __float_as_uint(v.w);
            }
            uint32_t bfr[8][2];
#pragma unroll
            for (int in = 0; in < 8; in++) {
                const float2 v = *(const float2*)(Bd + (ka * 16 + warp_n * 8 + in) * BBLK + lid * 2);
                bfr[in][0] = __float_as_uint(v.x); bfr[in][1] = __float_as_uint(v.y);
            }
#pragma unroll
            for (int im = 0; im < 2; im++)
#pragma unroll
                for (int in = 0; in < 8; in++)
                    mma_tf32(acc[im][in], afr[im], bfr[in]);
        }
        __syncthreads();
    }

    const int g = lid >> 2, cq = lid & 3;
#pragma unroll
    for (int im = 0; im < 2; im++) {
        const int mbase = bm + warp_m * 32 + im * 16 + g;
#pragma unroll
        for (int in = 0; in < 8; in++) {
            const int n0 = bn + warp_n * 64 + in * 8 + cq * 2;
            const float c0 = acc[im][in][0], c1 = acc[im][in][1];
            const float c2 = acc[im][in][2], c3 = acc[im][in][3];
            if (EPI == 0) {
                const float2 bv = *(const float2*)(bias + n0);
                const int h = n0 >> 6, d = n0 & 63;
#pragma unroll
                for (int rr = 0; rr < 2; rr++) {
                    const int m = mbase + rr * 8;
                    const int b = m >> 11, s = m & 2047;
                    float2 o; o.x = (rr ? c2 : c0) + bv.x; o.y = (rr ? c3 : c1) + bv.y;
                    *(float2*)&C[(((size_t)(b * NUM_HEADS + h) * SEQ) + s) * D_K + d] = o;
                }
            } else if (EPI == 1) {
                const float b0 = bias[n0], b1 = bias[n0 + 1];
                const int h = n0 >> 6, d = n0 & 63;
#pragma unroll
                for (int rr = 0; rr < 2; rr++) {
                    const int m = mbase + rr * 8;
                    const int b = m >> 11, s = m & 2047;
                    const size_t base = ((size_t)(b * NUM_HEADS + h) * D_K + d) * SEQ + s;
                    C[base]       = (rr ? c2 : c0) + b0;
                    C[base + SEQ] = (rr ? c3 : c1) + b1;
                }
            } else {
                const float2 bv = *(const float2*)(bias + n0);
#pragma unroll
                for (int rr = 0; rr < 2; rr++) {
                    const int m = mbase + rr * 8;
                    float2 o; o.x = (rr ? c2 : c0) + bv.x; o.y = (rr ? c3 : c1) + bv.y;
                    *(float2*)&C[(size_t)m * D_MODEL + n0] = o;
                }
            }
        }
    }
}

// ---------------------------------------------------------------------------
// Kernel S: scores + exp + row-sums. Writes UNNORMALIZED P (fp32) into attn
// buffer, and inv_l into g_l. 512 threads, 4x4 warp grid, warp tile 32x32.
// ---------------------------------------------------------------------------
#define S_Q    0                        // Q frags: 64*ABLK
#define S_K0   (64 * ABLK)
#define S_KB   (128 * BBLK)
#define S_PART (S_K0 + 2 * S_KB)        // 25344 (4 x 128)
#define S_TOT  (S_PART + 512)           // 25856 floats

__global__ void __launch_bounds__(512) scores_kernel(float* __restrict__ attn)
{
    extern __shared__ float smf[];
    const int tid = threadIdx.x;
    const int wid = tid >> 5, lid = tid & 31;
    const int warp_m = wid >> 2, warp_n = wid & 3;
    const int g = lid >> 2, cq = lid & 3;
    const int bm = blockIdx.x * 128;
    const int bh = blockIdx.y;

    const float* qp = g_q + (size_t)bh * SEQ * D_K + (size_t)bm * D_K;
    const float* kp = g_k + (size_t)bh * SEQ * D_K;
    float* ap = attn + (size_t)bh * SEQ * SEQ;

    // stage Q tile into A-frag layout
#pragma unroll
    for (int it = 0; it < 4; it++) {
        int f = tid + it * 512;
        int row = f >> 4, c4 = f & 15;
        float4 v = *(const float4*)(qp + (size_t)row * D_K + c4 * 4);
        int ma = row >> 4, r = row & 15;
        int ka = c4 >> 1;
        int slot = ((c4 & 1) << 1) | (r >> 3);
        float* p = smf + S_Q + ((ka * 8 + ma) * ABLK + ((r & 7) << 4) + slot);
        p[0]  = __uint_as_float(rn_tf32(v.x));
        p[4]  = __uint_as_float(rn_tf32(v.y));
        p[8]  = __uint_as_float(rn_tf32(v.z));
        p[12] = __uint_as_float(rn_tf32(v.w));
    }

    float4 rk[4];
    auto ldg_k = [&](int t) {
        const float* kb = kp + (size_t)(t * 128) * D_K;
#pragma unroll
        for (int it = 0; it < 4; it++) {
            int f = tid + it * 512;
            int row = f >> 4, c4 = f & 15;
            rk[it] = *(const float4*)(kb + (size_t)row * D_K + c4 * 4);
        }
    };
    auto sts_k = [&](int buf) {
        float* db = smf + S_K0 + buf * S_KB;
#pragma unroll
        for (int it = 0; it < 4; it++) {
            int f = tid + it * 512;
            int row = f >> 4, c4 = f & 15;
            int na = row >> 3, nn = row & 7;
            int ka = c4 >> 1, slot = c4 & 1;
            float* p = db + ((ka * 16 + na) * BBLK + (nn << 3) + slot);
            p[0] = __uint_as_float(rn_tf32(rk[it].x));
            p[2] = __uint_as_float(rn_tf32(rk[it].y));
            p[4] = __uint_as_float(rn_tf32(rk[it].z));
            p[6] = __uint_as_float(rn_tf32(rk[it].w));
        }
    };

    float racc[2][2] = {{0.f, 0.f}, {0.f, 0.f}};

    ldg_k(0); sts_k(0); ldg_k(1);
    __syncthreads();

    for (int t = 0; t < 16; t++) {
        if (t + 1 < 16) sts_k((t + 1) & 1);
        if (t + 2 < 16) ldg_k(t + 2);

        float acc[2][4][4];
#pragma unroll
        for (int im = 0; im < 2; im++)
#pragma unroll
            for (int in = 0; in < 4; in++)
#pragma unroll
                for (int c = 0; c < 4; c++) acc[im][in][c] = 0.f;

        const float* Kd = smf + S_K0 + (t & 1) * S_KB;
#pragma unroll
        for (int ka = 0; ka < 8; ka++) {
            uint32_t afr[2][4];
#pragma unroll
            for (int im = 0; im < 2; im++) {
                const float4 v = *(const float4*)(smf + S_Q + (ka * 8 + warp_m * 2 + im) * ABLK + lid * 4);
                afr[im][0] = __float_as_uint(v.x); afr[im][1] = __float_as_uint(v.y);
                afr[im][2] = __float_as_uint(v.z); afr[im][3] = __float_as_uint(v.w);
            }
            uint32_t bfr[4][2];
#pragma unroll
            for (int in = 0; in < 4; in++) {
                const float2 v = *(const float2*)(Kd + (ka * 16 + warp_n * 4 + in) * BBLK + lid * 2);
                bfr[in][0] = __float_as_uint(v.x); bfr[in][1] = __float_as_uint(v.y);
            }
#pragma unroll
            for (int im = 0; im < 2; im++)
#pragma unroll
                for (int in = 0; in < 4; in++)
                    mma_tf32(acc[im][in], afr[im], bfr[in]);
        }

        // exp + row sums + unnormalized P store (fp32, streaming)
#pragma unroll
        for (int im = 0; im < 2; im++) {
            const int mrow = bm + warp_m * 32 + im * 16 + g;
#pragma unroll
            for (int in = 0; in < 4; in++) {
                const int col = t * 128 + warp_n * 32 + in * 8 + cq * 2;
                const float e0 = __expf(acc[im][in][0] * 0.125f);
                const float e1 = __expf(acc[im][in][1] * 0.125f);
                const float e2 = __expf(acc[im][in][2] * 0.125f);
                const float e3 = __expf(acc[im][in][3] * 0.125f);
                racc[im][0] += e0 + e1;
                racc[im][1] += e2 + e3;
                __stcs((float2*)&ap[(size_t)mrow * SEQ + col], make_float2(e0, e1));
                __stcs((float2*)&ap[(size_t)(mrow + 8) * SEQ + col], make_float2(e2, e3));
            }
        }
        __syncthreads();
    }

    // row-sum reduction -> inverse l
#pragma unroll
    for (int im = 0; im < 2; im++)
#pragma unroll
        for (int rr = 0; rr < 2; rr++) {
            float s = racc[im][rr];
            s += __shfl_xor_sync(0xffffffffu, s, 1);
            s += __shfl_xor_sync(0xffffffffu, s, 2);
            if (cq == 0)
                smf[S_PART + warp_n * 128 + warp_m * 32 + im * 16 + rr * 8 + g] = s;
        }
    __syncthreads();
    if (tid < 128) {
        float l = smf[S_PART + tid] + smf[S_PART + 128 + tid] +
                  smf[S_PART + 256 + tid] + smf[S_PART + 384 + tid];
        g_l[(size_t)bh * SEQ + bm + tid] = 1.f / l;
    }
}

// ---------------------------------------------------------------------------
// Kernel C: ctx = P @ V^T, and in-place normalize P -> attn (x inv_l).
// Reads unnormalized P from gmem (coalesced), stages to A-frag smem (tf32),
// 512 threads, 4x4 warp grid, ctx warp tile 32 rows x 16 d.
// ---------------------------------------------------------------------------
#define C_P0  0                         // 2 x 128*ABLK = 2 x 16896
#define C_PB  (128 * ABLK)
#define C_V0  (2 * C_PB)                // 33792; 2 x 128*BBLK = 2 x 8448
#define C_VB  (128 * BBLK)
#define C_TOT (C_V0 + 2 * C_VB)         // 50688 floats = 202752 B

__global__ void __launch_bounds__(512) ctx_kernel(float* __restrict__ attn)
{
    extern __shared__ float smf[];
    const int tid = threadIdx.x;
    const int wid = tid >> 5, lid = tid & 31;
    const int warp_m = wid >> 2, warp_n = wid & 3;
    const int g = lid >> 2, cq = lid & 3;
    const int bm = blockIdx.x * 128;
    const int bh = blockIdx.y;

    const float* vp = g_vt + (size_t)bh * D_K * SEQ;
    float* ap = attn + (size_t)bh * SEQ * SEQ;
    const float* lp = g_l + (size_t)bh * SEQ + bm;   // inverse l

    // per-thread fixed row assignments for P staging
    float rinv[8];
#pragma unroll
    for (int it = 0; it < 8; it++) {
        int f = tid + it * 512;
        rinv[it] = __ldg(&lp[f >> 5]);
    }

    float4 rp[8];
    auto ldg_p = [&](int t) {
#pragma unroll
        for (int it = 0; it < 8; it++) {
            int f = tid + it * 512;
            int row = f >> 5, c4 = f & 31;
            rp[it] = __ldcs((const float4*)&ap[(size_t)(bm + row) * SEQ + t * 128 + c4 * 4]);
        }
    };
    auto sts_p = [&](int t, int buf) {
        float* dp = smf + C_P0 + buf * C_PB;
#pragma unroll
        for (int it = 0; it < 8; it++) {
            int f = tid + it * 512;
            int row = f >> 5, c4 = f & 31;
            // normalized write-back (fp32)
            float4 o;
            o.x = rp[it].x * rinv[it]; o.y = rp[it].y * rinv[it];
            o.z = rp[it].z * rinv[it]; o.w = rp[it].w * rinv[it];
            __stcs((float4*)&ap[(size_t)(bm + row) * SEQ + t * 128 + c4 * 4], o);
            // tf32 A-frag staging (unnormalized; epilogue applies inv)
            int r = row & 15, ka = c4 >> 1;
            int slot = ((c4 & 1) << 1) | (r >> 3);
            float* p = dp + ((ka * 8 + (row >> 4)) * ABLK + ((r & 7) << 4) + slot);
            p[0]  = __uint_as_float(rn_tf32(rp[it].x));
            p[4]  = __uint_as_float(rn_tf32(rp[it].y));
            p[8]  = __uint_as_float(rn_tf32(rp[it].z));
            p[12] = __uint_as_float(rn_tf32(rp[it].w));
        }
    };

    float4 rv[4];
    auto ldg_v = [&](int t) {
        const float* vb = vp + t * 128;
#pragma unroll
        for (int it = 0; it < 4; it++) {
            int f = tid + it * 512;
            int row = f >> 5, c4 = f & 31;
            rv[it] = *(const float4*)(vb + (size_t)row * SEQ + c4 * 4);
        }
    };
    auto sts_v = [&](int buf) {
        float* dv = smf + C_V0 + buf * C_VB;
#pragma unroll
        for (int it = 0; it < 4; it++) {
            int f = tid + it * 512;
            int row = f >> 5, c4 = f & 31;
            int na = row >> 3, nn = row & 7;
            int ka = c4 >> 1, slot = c4 & 1;
            float* p = dv + ((ka * 8 + na) * BBLK + (nn << 3) + slot);
            p[0] = __uint_as_float(rn_tf32(rv[it].x));
            p[2] = __uint_as_float(rn_tf32(rv[it].y));
            p[4] = __uint_as_float(rn_tf32(rv[it].z));
            p[6] = __uint_as_float(rn_tf32(rv[it].w));
        }
    };

    float acc2[2][2][4];
#pragma unroll
    for (int im = 0; im < 2; im++)
#pragma unroll
        for (int in = 0; in < 2; in++)
#pragma unroll
            for (int c = 0; c < 4; c++) acc2[im][in][c] = 0.f;

    ldg_p(0); ldg_v(0);
    sts_p(0, 0); sts_v(0);
    ldg_p(1); ldg_v(1);
    __syncthreads();

    for (int t = 0; t < 16; t++) {
        if (t + 1 < 16) { sts_p(t + 1, (t + 1) & 1); sts_v((t + 1) & 1); }
        if (t + 2 < 16) { ldg_p(t + 2); ldg_v(t + 2); }

        const float* Pd = smf + C_P0 + (t & 1) * C_PB;
        const float* Vd = smf + C_V0 + (t & 1) * C_VB;
#pragma unroll
        for (int kg = 0; kg < 16; kg++) {
            uint32_t afr[2][4];
#pragma unroll
            for (int im = 0; im < 2; im++) {
                const float4 v = *(const float4*)(Pd + (kg * 8 + warp_m * 2 + im) * ABLK + lid * 4);
                afr[im][0] = __float_as_uint(v.x); afr[im][1] = __float_as_uint(v.y);
                afr[im][2] = __float_as_uint(v.z); afr[im][3] = __float_as_uint(v.w);
            }
#pragma unroll
            for (int in = 0; in < 2; in++) {
                uint32_t bfr[2];
                const float2 v = *(const float2*)(Vd + (kg * 8 + warp_n * 2 + in) * BBLK + lid * 2);
                bfr[0] = __float_as_uint(v.x); bfr[1] = __float_as_uint(v.y);
#pragma unroll
                for (int im = 0; im < 2; im++)
                    mma_tf32(acc2[im][in], afr[im], bfr);
            }
        }
        __syncthreads();
    }

    // ctx epilogue: scale by inv_l, scatter to g_ctx
    const int b = bh >> 4, h = bh & 15;
#pragma unroll
    for (int im = 0; im < 2; im++) {
#pragma unroll
        for (int rr = 0; rr < 2; rr++) {
            const int rowl = warp_m * 32 + im * 16 + g + rr * 8;
            const float inv = __ldg(&lp[rowl]);
            const int srow = bm + rowl;
#pragma unroll
            for (int in = 0; in < 2; in++) {
                const int n0 = warp_n * 16 + in * 8 + cq * 2;
                float2 o;
                o.x = acc2[im][in][rr ? 2 : 0] * inv;
                o.y = acc2[im][in][rr ? 3 : 1] * inv;
                *(float2*)&g_ctx[((size_t)(b * SEQ + srow)) * D_MODEL + h * D_K + n0] = o;
            }
        }
    }
}

extern "C" void kernel_launch(void* const* d_in, const int* in_sizes, int n_in,
                              void* d_out, int out_size) {
    const float* Q  = (const float*)d_in[0];
    const float* K  = (const float*)d_in[1];
    const float* V  = (const float*)d_in[2];
    const float* Wq = (const float*)d_in[3];
    const float* bq = (const float*)d_in[4];
    const float* Wk = (const float*)d_in[5];
    const float* bk = (const float*)d_in[6];
    const float* Wv = (const float*)d_in[7];
    const float* bv = (const float*)d_in[8];
    const float* Wo = (const float*)d_in[9];
    const float* bo = (const float*)d_in[10];

    float* out = (float*)d_out;

    const size_t OUT_ELEMS  = (size_t)M_ROWS * D_MODEL;
    const size_t ATTN_ELEMS = (size_t)BH * SEQ * SEQ;

    float* attn;
    if ((size_t)out_size >= OUT_ELEMS + ATTN_ELEMS) {
        attn = out + OUT_ELEMS;
    } else {
        void* p = nullptr;
        cudaGetSymbolAddress(&p, g_attn_fb);
        attn = (float*)p;
    }

    float *qp, *kp, *vtp, *cp;
    { void* t; cudaGetSymbolAddress(&t, g_q);   qp  = (float*)t; }
    { void* t; cudaGetSymbolAddress(&t, g_k);   kp  = (float*)t; }
    { void* t; cudaGetSymbolAddress(&t, g_vt);  vtp = (float*)t; }
    { void* t; cudaGetSymbolAddress(&t, g_ctx); cp  = (float*)t; }

    const int SMP = (2 * 32 * ABLK + 2 * 64 * BBLK) * 4;
    const int SMS = S_TOT * 4;
    const int SMC = C_TOT * 4;

    cudaFuncSetAttribute(mma_gemm<0>, cudaFuncAttributeMaxDynamicSharedMemorySize, SMP);
    cudaFuncSetAttribute(mma_gemm<1>, cudaFuncAttributeMaxDynamicSharedMemorySize, SMP);
    cudaFuncSetAttribute(mma_gemm<2>, cudaFuncAttributeMaxDynamicSharedMemorySize, SMP);
    cudaFuncSetAttribute(scores_kernel, cudaFuncAttributeMaxDynamicSharedMemorySize, SMS);
    cudaFuncSetAttribute(ctx_kernel, cudaFuncAttributeMaxDynamicSharedMemorySize, SMC);

    dim3 projGrid(D_MODEL / 128, M_ROWS / 128);     // (8, 64)
    mma_gemm<0><<<projGrid, 256, SMP>>>(Q, Wq, bq, qp, 1024, 1024, 1024);
    mma_gemm<0><<<projGrid, 256, SMP>>>(K, Wk, bk, kp, 1024, 1024, 1024);
    mma_gemm<1><<<projGrid, 256, SMP>>>(V, Wv, bv, vtp, 1024, 1024, 1024);

    dim3 attGrid(SEQ / 128, BH);                    // (16, 64)
    scores_kernel<<<attGrid, 512, SMS>>>(attn);
    ctx_kernel<<<attGrid, 512, SMC>>>(attn);

    mma_gemm<2><<<projGrid, 256, SMP>>>(cp, Wo, bo, out, 1024, 1024, 1024);
}

// round 9
// speedup vs baseline: 1.1854x; 1.1854x over previous
#include <cuda_runtime.h>
#include <cstdint>

#define D_MODEL 1024
#define NUM_HEADS 16
#define D_K 64
#define BATCH 4
#define SEQ 2048
#define BH (BATCH * NUM_HEADS)          // 64
#define M_ROWS (BATCH * SEQ)            // 8192

// Scratch (device globals; no dynamic allocation allowed)
__device__ float g_q[(size_t)BH * SEQ * D_K];
__device__ float g_k[(size_t)BH * SEQ * D_K];
__device__ float g_vt[(size_t)BH * D_K * SEQ];   // V transposed: [bh][d][s]
__device__ float g_ctx[(size_t)M_ROWS * D_MODEL];
__device__ float g_l[(size_t)BH * SEQ];          // INVERSE softmax row sums
__device__ float g_attn_fb[(size_t)BH * SEQ * SEQ];

// Round fp32 -> tf32 (round-to-nearest; HMMA then truncates losslessly)
__device__ __forceinline__ uint32_t rn_tf32(float x) {
    return (__float_as_uint(x) + 0x1000u) & 0xFFFFE000u;
}

__device__ __forceinline__ void mma_tf32(float* d, const uint32_t* a, const uint32_t* b) {
    asm volatile(
        "mma.sync.aligned.m16n8k8.row.col.f32.tf32.tf32.f32 "
        "{%0,%1,%2,%3}, {%4,%5,%6,%7}, {%8,%9}, {%0,%1,%2,%3};"
        : "+f"(d[0]), "+f"(d[1]), "+f"(d[2]), "+f"(d[3])
        : "r"(a[0]), "r"(a[1]), "r"(a[2]), "r"(a[3]), "r"(b[0]), "r"(b[1]));
}

// Fragment smem block strides (padded to break STS bank conflicts)
#define ABLK 132   // 128 floats + 4 pad
#define BBLK 66    // 64 floats + 2 pad

// ---------------------------------------------------------------------------
// Projection GEMM:  C = A(M x K, K-major) * B(N x K, K-major)^T   (tf32 MMA)
// Block tile 128 x 128, BK = 32, 256 threads, warps 4x2, 2 CTAs/SM.
// EPI: 0 = split-heads Q/K (+bias), 1 = V transposed (+bias), 2 = row-major (+bias)
// ---------------------------------------------------------------------------
template <int EPI>
__global__ void __launch_bounds__(256, 2) mma_gemm(
    const float* __restrict__ A, const float* __restrict__ B,
    const float* __restrict__ bias, float* __restrict__ C,
    int K, int lda, int ldb)
{
    constexpr int A_FLOATS = 32 * ABLK;
    constexpr int B_FLOATS = 64 * BBLK;

    extern __shared__ float smf[];
    float* As = smf;
    float* Bs = smf + 2 * A_FLOATS;

    const int tid = threadIdx.x;
    const int wid = tid >> 5, lid = tid & 31;
    const int warp_m = wid >> 1, warp_n = wid & 1;
    const int bm = blockIdx.y * 128;
    const int bn = blockIdx.x * 128;

    const float* Ab = A + (size_t)bm * lda;
    const float* Bb = B + (size_t)bn * ldb;

    float4 ra[4], rb[4];

    auto ldg_tiles = [&](int k0) {
#pragma unroll
        for (int it = 0; it < 4; it++) {
            int f = tid + it * 256;
            int row = f >> 3, k4 = f & 7;
            ra[it] = *(const float4*)(Ab + (size_t)row * lda + k0 + k4 * 4);
            rb[it] = *(const float4*)(Bb + (size_t)row * ldb + k0 + k4 * 4);
        }
    };

    auto sts_tiles = [&](int buf) {
        float* da = As + buf * A_FLOATS;
        float* db = Bs + buf * B_FLOATS;
#pragma unroll
        for (int it = 0; it < 4; it++) {
            int f = tid + it * 256;
            int row = f >> 3, k4 = f & 7;
            {
                int ma = row >> 4, r = row & 15;
                int ka = k4 >> 1;
                int slot = ((k4 & 1) << 1) | (r >> 3);
                float* p = da + ((ka * 8 + ma) * ABLK + ((r & 7) << 4) + slot);
                p[0]  = __uint_as_float(rn_tf32(ra[it].x));
                p[4]  = __uint_as_float(rn_tf32(ra[it].y));
                p[8]  = __uint_as_float(rn_tf32(ra[it].z));
                p[12] = __uint_as_float(rn_tf32(ra[it].w));
            }
            {
                int na = row >> 3, nn = row & 7;
                int ka = k4 >> 1;
                int slot = k4 & 1;
                float* p = db + ((ka * 16 + na) * BBLK + (nn << 3) + slot);
                p[0] = __uint_as_float(rn_tf32(rb[it].x));
                p[2] = __uint_as_float(rn_tf32(rb[it].y));
                p[4] = __uint_as_float(rn_tf32(rb[it].z));
                p[6] = __uint_as_float(rn_tf32(rb[it].w));
            }
        }
    };

    float acc[2][8][4];
#pragma unroll
    for (int im = 0; im < 2; im++)
#pragma unroll
        for (int in = 0; in < 8; in++)
#pragma unroll
            for (int c = 0; c < 4; c++) acc[im][in][c] = 0.f;

    const int KS = K >> 5;
    ldg_tiles(0);
    sts_tiles(0);
    ldg_tiles(32);
    __syncthreads();

    for (int ks = 0; ks < KS; ks++) {
        if (ks + 1 < KS) sts_tiles((ks + 1) & 1);
        if (ks + 2 < KS) ldg_tiles((ks + 2) << 5);

        const float* Ad = As + (ks & 1) * A_FLOATS;
        const float* Bd = Bs + (ks & 1) * B_FLOATS;
#pragma unroll
        for (int ka = 0; ka < 4; ka++) {
            uint32_t afr[2][4];
#pragma unroll
            for (int im = 0; im < 2; im++) {
                const float4 v = *(const float4*)(Ad + (ka * 8 + warp_m * 2 + im) * ABLK + lid * 4);
                afr[im][0] = __float_as_uint(v.x); afr[im][1] = __float_as_uint(v.y);
                afr[im][2] = __float_as_uint(v.z); afr[im][3] = __float_as_uint(v.w);
            }
            uint32_t bfr[8][2];
#pragma unroll
            for (int in = 0; in < 8; in++) {
                const float2 v = *(const float2*)(Bd + (ka * 16 + warp_n * 8 + in) * BBLK + lid * 2);
                bfr[in][0] = __float_as_uint(v.x); bfr[in][1] = __float_as_uint(v.y);
            }
#pragma unroll
            for (int im = 0; im < 2; im++)
#pragma unroll
                for (int in = 0; in < 8; in++)
                    mma_tf32(acc[im][in], afr[im], bfr[in]);
        }
        __syncthreads();
    }

    const int g = lid >> 2, cq = lid & 3;
#pragma unroll
    for (int im = 0; im < 2; im++) {
        const int mbase = bm + warp_m * 32 + im * 16 + g;
#pragma unroll
        for (int in = 0; in < 8; in++) {
            const int n0 = bn + warp_n * 64 + in * 8 + cq * 2;
            const float c0 = acc[im][in][0], c1 = acc[im][in][1];
            const float c2 = acc[im][in][2], c3 = acc[im][in][3];
            if (EPI == 0) {
                const float2 bv = *(const float2*)(bias + n0);
                const int h = n0 >> 6, d = n0 & 63;
#pragma unroll
                for (int rr = 0; rr < 2; rr++) {
                    const int m = mbase + rr * 8;
                    const int b = m >> 11, s = m & 2047;
                    float2 o; o.x = (rr ? c2 : c0) + bv.x; o.y = (rr ? c3 : c1) + bv.y;
                    *(float2*)&C[(((size_t)(b * NUM_HEADS + h) * SEQ) + s) * D_K + d] = o;
                }
            } else if (EPI == 1) {
                const float b0 = bias[n0], b1 = bias[n0 + 1];
                const int h = n0 >> 6, d = n0 & 63;
#pragma unroll
                for (int rr = 0; rr < 2; rr++) {
                    const int m = mbase + rr * 8;
                    const int b = m >> 11, s = m & 2047;
                    const size_t base = ((size_t)(b * NUM_HEADS + h) * D_K + d) * SEQ + s;
                    C[base]       = (rr ? c2 : c0) + b0;
                    C[base + SEQ] = (rr ? c3 : c1) + b1;
                }
            } else {
                const float2 bv = *(const float2*)(bias + n0);
#pragma unroll
                for (int rr = 0; rr < 2; rr++) {
                    const int m = mbase + rr * 8;
                    float2 o; o.x = (rr ? c2 : c0) + bv.x; o.y = (rr ? c3 : c1) + bv.y;
                    *(float2*)&C[(size_t)m * D_MODEL + n0] = o;
                }
            }
        }
    }
}

// ---------------------------------------------------------------------------
// flashA v3: fused scores + exp + row-sum + ctx, 512 threads (16 warps).
// Scores: warp grid 4m x 4n, warp tile 32x32. ctx: warp tile 32 rows x 16 d.
// P goes through smem in A-frag layout (float2 stores, conflict-padded).
// Stores INVERSE row sums to g_l.
// ---------------------------------------------------------------------------
#define FB_Q    0                        // Q frags: 64*ABLK = 8448
#define FB_K0   (64 * ABLK)              // 8448
#define FB_KB   (128 * BBLK)             // 8448 per K buffer
#define FB_P    (FB_K0 + 2 * FB_KB)      // 25344, P frags 128*ABLK = 16896
#define FB_V    (FB_P + 128 * ABLK)      // 42240, V frags 128*BBLK = 8448
#define FB_PART (FB_V + 128 * BBLK)      // 50688 (4 x 128)
#define FB_LSUM (FB_PART + 512)          // 51200
#define FB_TOT  (FB_LSUM + 128)          // 51328 floats = 205312 B

__global__ void __launch_bounds__(512) flash_kernel()
{
    extern __shared__ float smf[];
    const int tid = threadIdx.x;
    const int wid = tid >> 5, lid = tid & 31;
    const int warp_m = wid >> 2, warp_n = wid & 3;   // 4 x 4 warp grid
    const int g = lid >> 2, cq = lid & 3;
    const int bm = blockIdx.x * 128;
    const int bh = blockIdx.y;

    const float* qp = g_q + (size_t)bh * SEQ * D_K + (size_t)bm * D_K;
    const float* kp = g_k + (size_t)bh * SEQ * D_K;
    const float* vp = g_vt + (size_t)bh * D_K * SEQ;

    // ---- stage Q tile into A-frag layout (rows 128 x k 64) ----
#pragma unroll
    for (int it = 0; it < 4; it++) {
        int f = tid + it * 512;
        int row = f >> 4, c4 = f & 15;
        float4 v = *(const float4*)(qp + (size_t)row * D_K + c4 * 4);
        int ma = row >> 4, r = row & 15;
        int ka = c4 >> 1;
        int slot = ((c4 & 1) << 1) | (r >> 3);
        float* p = smf + FB_Q + ((ka * 8 + ma) * ABLK + ((r & 7) << 4) + slot);
        p[0]  = __uint_as_float(rn_tf32(v.x));
        p[4]  = __uint_as_float(rn_tf32(v.y));
        p[8]  = __uint_as_float(rn_tf32(v.z));
        p[12] = __uint_as_float(rn_tf32(v.w));
    }

    float4 rk[4];
    auto ldg_k = [&](int t) {
        const float* kb = kp + (size_t)(t * 128) * D_K;
#pragma unroll
        for (int it = 0; it < 4; it++) {
            int f = tid + it * 512;
            int row = f >> 4, c4 = f & 15;
            rk[it] = *(const float4*)(kb + (size_t)row * D_K + c4 * 4);
        }
    };
    auto sts_k = [&](int buf) {
        float* db = smf + FB_K0 + buf * FB_KB;
#pragma unroll
        for (int it = 0; it < 4; it++) {
            int f = tid + it * 512;
            int row = f >> 4, c4 = f & 15;
            int na = row >> 3, nn = row & 7;
            int ka = c4 >> 1, slot = c4 & 1;
            float* p = db + ((ka * 16 + na) * BBLK + (nn << 3) + slot);
            p[0] = __uint_as_float(rn_tf32(rk[it].x));
            p[2] = __uint_as_float(rn_tf32(rk[it].y));
            p[4] = __uint_as_float(rn_tf32(rk[it].z));
            p[6] = __uint_as_float(rn_tf32(rk[it].w));
        }
    };

    float4 rv[2];
    auto ldg_v = [&](int t, int half) {
        const float* vb = vp + t * 128;
#pragma unroll
        for (int it = 0; it < 2; it++) {
            int f = tid + (half * 2 + it) * 512;
            int row = f >> 5, c4 = f & 31;
            rv[it] = *(const float4*)(vb + (size_t)row * SEQ + c4 * 4);
        }
    };
    auto sts_v = [&](int half) {
#pragma unroll
        for (int it = 0; it < 2; it++) {
            int f = tid + (half * 2 + it) * 512;
            int row = f >> 5, c4 = f & 31;
            int na = row >> 3, nn = row & 7;
            int ka = c4 >> 1, slot = c4 & 1;
            float* p = smf + FB_V + ((ka * 8 + na) * BBLK + (nn << 3) + slot);
            p[0] = __uint_as_float(rn_tf32(rv[it].x));
            p[2] = __uint_as_float(rn_tf32(rv[it].y));
            p[4] = __uint_as_float(rn_tf32(rv[it].z));
            p[6] = __uint_as_float(rn_tf32(rv[it].w));
        }
    };

    // ctx accumulator: warp tile 32 rows x 16 d-cols
    float acc2[2][2][4];
#pragma unroll
    for (int im = 0; im < 2; im++)
#pragma unroll
        for (int in = 0; in < 2; in++)
#pragma unroll
            for (int c = 0; c < 4; c++) acc2[im][in][c] = 0.f;
    float racc[2][2] = {{0.f, 0.f}, {0.f, 0.f}};

    ldg_k(0); sts_k(0); ldg_k(1);
    __syncthreads();

    for (int t = 0; t < 16; t++) {
        if (t + 1 < 16) sts_k((t + 1) & 1);
        if (t + 2 < 16) ldg_k(t + 2);

        // ---- scores MMA: warp tile 32 rows x 32 cols ----
        float acc[2][4][4];
#pragma unroll
        for (int im = 0; im < 2; im++)
#pragma unroll
            for (int in = 0; in < 4; in++)
#pragma unroll
                for (int c = 0; c < 4; c++) acc[im][in][c] = 0.f;

        const float* Kd = smf + FB_K0 + (t & 1) * FB_KB;
#pragma unroll
        for (int ka = 0; ka < 8; ka++) {
            uint32_t afr[2][4];
#pragma unroll
            for (int im = 0; im < 2; im++) {
                const float4 v = *(const float4*)(smf + FB_Q + (ka * 8 + warp_m * 2 + im) * ABLK + lid * 4);
                afr[im][0] = __float_as_uint(v.x); afr[im][1] = __float_as_uint(v.y);
                afr[im][2] = __float_as_uint(v.z); afr[im][3] = __float_as_uint(v.w);
            }
            uint32_t bfr[4][2];
#pragma unroll
            for (int in = 0; in < 4; in++) {
                const float2 v = *(const float2*)(Kd + (ka * 16 + warp_n * 4 + in) * BBLK + lid * 2);
                bfr[in][0] = __float_as_uint(v.x); bfr[in][1] = __float_as_uint(v.y);
            }
#pragma unroll
            for (int im = 0; im < 2; im++)
#pragma unroll
                for (int in = 0; in < 4; in++)
                    mma_tf32(acc[im][in], afr[im], bfr[in]);
        }

        // ---- e = exp(s/8); row sums; float2 scatter to P-frag ----
#pragma unroll
        for (int im = 0; im < 2; im++) {
            ldg_v(t, im);
            const int row_blk = warp_m * 2 + im;           // 16-row block idx
#pragma unroll
            for (int in = 0; in < 4; in++) {
                const int col0 = warp_n * 32 + in * 8 + cq * 2;
#pragma unroll
                for (int j2 = 0; j2 < 2; j2++) {
                    const int col = col0 + j2;
                    const float e0 = __expf(acc[im][in][j2] * 0.125f);
                    const float e1 = __expf(acc[im][in][2 + j2] * 0.125f);
                    racc[im][0] += e0;
                    racc[im][1] += e1;
                    const int kk = col & 7;
                    const int word = ((col >> 3) * 8 + row_blk) * ABLK +
                                     g * 16 + (kk & 3) * 4 + ((kk >> 2) << 1);
                    float2 o; o.x = __uint_as_float(rn_tf32(e0));
                    o.y = __uint_as_float(rn_tf32(e1));
                    *(float2*)(smf + FB_P + word) = o;
                }
            }
            sts_v(im);
        }
        __syncthreads();

        // ---- ctx MMA: warp tile 32 rows x 16 d, k = 128 (16 atoms) ----
#pragma unroll
        for (int kg = 0; kg < 16; kg++) {
            uint32_t afr[2][4];
#pragma unroll
            for (int im = 0; im < 2; im++) {
                const float4 v = *(const float4*)(smf + FB_P + (kg * 8 + warp_m * 2 + im) * ABLK + lid * 4);
                afr[im][0] = __float_as_uint(v.x); afr[im][1] = __float_as_uint(v.y);
                afr[im][2] = __float_as_uint(v.z); afr[im][3] = __float_as_uint(v.w);
            }
#pragma unroll
            for (int in = 0; in < 2; in++) {
                uint32_t bfr[2];
                const float2 v = *(const float2*)(smf + FB_V + (kg * 8 + warp_n * 2 + in) * BBLK + lid * 2);
                bfr[0] = __float_as_uint(v.x); bfr[1] = __float_as_uint(v.y);
#pragma unroll
                for (int im = 0; im < 2; im++)
                    mma_tf32(acc2[im][in], afr[im], bfr);
            }
        }
        __syncthreads();
    }

    // ---- finalize row sums (deterministic reduction), store INVERSE ----
#pragma unroll
    for (int im = 0; im < 2; im++)
#pragma unroll
        for (int rr = 0; rr < 2; rr++) {
            float s = racc[im][rr];
            s += __shfl_xor_sync(0xffffffffu, s, 1);
            s += __shfl_xor_sync(0xffffffffu, s, 2);
            if (cq == 0)
                smf[FB_PART + warp_n * 128 + warp_m * 32 + im * 16 + rr * 8 + g] = s;
        }
    __syncthreads();
    if (tid < 128) {
        float l = smf[FB_PART + tid] + smf[FB_PART + 128 + tid] +
                  smf[FB_PART + 256 + tid] + smf[FB_PART + 384 + tid];
        float inv = 1.f / l;
        smf[FB_LSUM + tid] = inv;
        g_l[(size_t)bh * SEQ + bm + tid] = inv;
    }
    __syncthreads();

    // ---- ctx epilogue: scale by inv_l, scatter to g_ctx ----
    const int b = bh >> 4, h = bh & 15;
#pragma unroll
    for (int im = 0; im < 2; im++) {
#pragma unroll
        for (int rr = 0; rr < 2; rr++) {
            const int rowl = warp_m * 32 + im * 16 + g + rr * 8;
            const float inv = smf[FB_LSUM + rowl];
            const int srow = bm + rowl;
#pragma unroll
            for (int in = 0; in < 2; in++) {
                const int n0 = warp_n * 16 + in * 8 + cq * 2;
                float2 o;
                o.x = acc2[im][in][rr ? 2 : 0] * inv;
                o.y = acc2[im][in][rr ? 3 : 1] * inv;
                *(float2*)&g_ctx[((size_t)(b * SEQ + srow)) * D_MODEL + h * D_K + n0] = o;
            }
        }
    }
}

// ---------------------------------------------------------------------------
// attnW (512 threads): recompute scores, write attn = exp(s/8) * inv_l.
// Warp grid 4x4, warp tile 32x32. Write-once, streaming stores.
// ---------------------------------------------------------------------------
#define AW_Q    0
#define AW_K0   (64 * ABLK)
#define AW_KB   (128 * BBLK)
#define AW_INV  (AW_K0 + 2 * AW_KB)     // 25344
#define AW_TOT  (AW_INV + 128)          // 25472 floats

__global__ void __launch_bounds__(512) attnw_kernel(float* __restrict__ attn)
{
    extern __shared__ float smf[];
    const int tid = threadIdx.x;
    const int wid = tid >> 5, lid = tid & 31;
    const int warp_m = wid >> 2, warp_n = wid & 3;
    const int g = lid >> 2, cq = lid & 3;
    const int bm = blockIdx.x * 128;
    const int bh = blockIdx.y;

    const float* qp = g_q + (size_t)bh * SEQ * D_K + (size_t)bm * D_K;
    const float* kp = g_k + (size_t)bh * SEQ * D_K;
    float* ap = attn + (size_t)bh * SEQ * SEQ;

    if (tid < 128)
        smf[AW_INV + tid] = g_l[(size_t)bh * SEQ + bm + tid];   // already inverse

    // stage Q tile into A-frag layout
#pragma unroll
    for (int it = 0; it < 4; it++) {
        int f = tid + it * 512;
        int row = f >> 4, c4 = f & 15;
        float4 v = *(const float4*)(qp + (size_t)row * D_K + c4 * 4);
        int ma = row >> 4, r = row & 15;
        int ka = c4 >> 1;
        int slot = ((c4 & 1) << 1) | (r >> 3);
        float* p = smf + AW_Q + ((ka * 8 + ma) * ABLK + ((r & 7) << 4) + slot);
        p[0]  = __uint_as_float(rn_tf32(v.x));
        p[4]  = __uint_as_float(rn_tf32(v.y));
        p[8]  = __uint_as_float(rn_tf32(v.z));
        p[12] = __uint_as_float(rn_tf32(v.w));
    }

    float4 rk[4];
    auto ldg_k = [&](int t) {
        const float* kb = kp + (size_t)(t * 128) * D_K;
#pragma unroll
        for (int it = 0; it < 4; it++) {
            int f = tid + it * 512;
            int row = f >> 4, c4 = f & 15;
            rk[it] = *(const float4*)(kb + (size_t)row * D_K + c4 * 4);
        }
    };
    auto sts_k = [&](int buf) {
        float* db = smf + AW_K0 + buf * AW_KB;
#pragma unroll
        for (int it = 0; it < 4; it++) {
            int f = tid + it * 512;
            int row = f >> 4, c4 = f & 15;
            int na = row >> 3, nn = row & 7;
            int ka = c4 >> 1, slot = c4 & 1;
            float* p = db + ((ka * 16 + na) * BBLK + (nn << 3) + slot);
            p[0] = __uint_as_float(rn_tf32(rk[it].x));
            p[2] = __uint_as_float(rn_tf32(rk[it].y));
            p[4] = __uint_as_float(rn_tf32(rk[it].z));
            p[6] = __uint_as_float(rn_tf32(rk[it].w));
        }
    };

    ldg_k(0); sts_k(0); ldg_k(1);
    __syncthreads();

    const int row0q = warp_m * 32 + g;
    const float iv0 = smf[AW_INV + row0q];
    const float iv1 = smf[AW_INV + row0q + 8];
    const float iv2 = smf[AW_INV + row0q + 16];
    const float iv3 = smf[AW_INV + row0q + 24];

    for (int t = 0; t < 16; t++) {
        if (t + 1 < 16) sts_k((t + 1) & 1);
        if (t + 2 < 16) ldg_k(t + 2);

        float acc[2][4][4];
#pragma unroll
        for (int im = 0; im < 2; im++)
#pragma unroll
            for (int in = 0; in < 4; in++)
#pragma unroll
                for (int c = 0; c < 4; c++) acc[im][in][c] = 0.f;

        const float* Kd = smf + AW_K0 + (t & 1) * AW_KB;
#pragma unroll
        for (int ka = 0; ka < 8; ka++) {
            uint32_t afr[2][4];
#pragma unroll
            for (int im = 0; im < 2; im++) {
                const float4 v = *(const float4*)(smf + AW_Q + (ka * 8 + warp_m * 2 + im) * ABLK + lid * 4);
                afr[im][0] = __float_as_uint(v.x); afr[im][1] = __float_as_uint(v.y);
                afr[im][2] = __float_as_uint(v.z); afr[im][3] = __float_as_uint(v.w);
            }
            uint32_t bfr[4][2];
#pragma unroll
            for (int in = 0; in < 4; in++) {
                const float2 v = *(const float2*)(Kd + (ka * 16 + warp_n * 4 + in) * BBLK + lid * 2);
                bfr[in][0] = __float_as_uint(v.x); bfr[in][1] = __float_as_uint(v.y);
            }
#pragma unroll
            for (int im = 0; im < 2; im++)
#pragma unroll
                for (int in = 0; in < 4; in++)
                    mma_tf32(acc[im][in], afr[im], bfr[in]);
        }

#pragma unroll
        for (int im = 0; im < 2; im++) {
            const int mrow = bm + warp_m * 32 + im * 16 + g;
            const float a0 = im ? iv2 : iv0;
            const float a1 = im ? iv3 : iv1;
#pragma unroll
            for (int in = 0; in < 4; in++) {
                const int col = t * 128 + warp_n * 32 + in * 8 + cq * 2;
                float2 o0, o1;
                o0.x = __expf(acc[im][in][0] * 0.125f) * a0;
                o0.y = __expf(acc[im][in][1] * 0.125f) * a0;
                o1.x = __expf(acc[im][in][2] * 0.125f) * a1;
                o1.y = __expf(acc[im][in][3] * 0.125f) * a1;
                __stcs((float2*)&ap[(size_t)mrow * SEQ + col], o0);
                __stcs((float2*)&ap[(size_t)(mrow + 8) * SEQ + col], o1);
            }
        }
        __syncthreads();
    }
}

extern "C" void kernel_launch(void* const* d_in, const int* in_sizes, int n_in,
                              void* d_out, int out_size) {
    const float* Q  = (const float*)d_in[0];
    const float* K  = (const float*)d_in[1];
    const float* V  = (const float*)d_in[2];
    const float* Wq = (const float*)d_in[3];
    const float* bq = (const float*)d_in[4];
    const float* Wk = (const float*)d_in[5];
    const float* bk = (const float*)d_in[6];
    const float* Wv = (const float*)d_in[7];
    const float* bv = (const float*)d_in[8];
    const float* Wo = (const float*)d_in[9];
    const float* bo = (const float*)d_in[10];

    float* out = (float*)d_out;

    const size_t OUT_ELEMS  = (size_t)M_ROWS * D_MODEL;
    const size_t ATTN_ELEMS = (size_t)BH * SEQ * SEQ;

    float* attn;
    if ((size_t)out_size >= OUT_ELEMS + ATTN_ELEMS) {
        attn = out + OUT_ELEMS;
    } else {
        void* p = nullptr;
        cudaGetSymbolAddress(&p, g_attn_fb);
        attn = (float*)p;
    }

    float *qp, *kp, *vtp, *cp;
    { void* t; cudaGetSymbolAddress(&t, g_q);   qp  = (float*)t; }
    { void* t; cudaGetSymbolAddress(&t, g_k);   kp  = (float*)t; }
    { void* t; cudaGetSymbolAddress(&t, g_vt);  vtp = (float*)t; }
    { void* t; cudaGetSymbolAddress(&t, g_ctx); cp  = (float*)t; }

    const int SMP  = (2 * 32 * ABLK + 2 * 64 * BBLK) * 4;
    const int SMFA = FB_TOT * 4;
    const int SMAW = AW_TOT * 4;

    cudaFuncSetAttribute(mma_gemm<0>, cudaFuncAttributeMaxDynamicSharedMemorySize, SMP);
    cudaFuncSetAttribute(mma_gemm<1>, cudaFuncAttributeMaxDynamicSharedMemorySize, SMP);
    cudaFuncSetAttribute(mma_gemm<2>, cudaFuncAttributeMaxDynamicSharedMemorySize, SMP);
    cudaFuncSetAttribute(flash_kernel, cudaFuncAttributeMaxDynamicSharedMemorySize, SMFA);
    cudaFuncSetAttribute(attnw_kernel, cudaFuncAttributeMaxDynamicSharedMemorySize, SMAW);

    dim3 projGrid(D_MODEL / 128, M_ROWS / 128);     // (8, 64)
    mma_gemm<0><<<projGrid, 256, SMP>>>(Q, Wq, bq, qp, 1024, 1024, 1024);
    mma_gemm<0><<<projGrid, 256, SMP>>>(K, Wk, bk, kp, 1024, 1024, 1024);
    mma_gemm<1><<<projGrid, 256, SMP>>>(V, Wv, bv, vtp, 1024, 1024, 1024);

    dim3 attGrid(SEQ / 128, BH);                    // (16, 64)
    flash_kernel<<<attGrid, 512, SMFA>>>();
    attnw_kernel<<<attGrid, 512, SMAW>>>(attn);

    mma_gemm<2><<<projGrid, 256, SMP>>>(cp, Wo, bo, out, 1024, 1024, 1024);
}

// round 12
// speedup vs baseline: 1.1885x; 1.0026x over previous
#include <cuda_runtime.h>
#include <cstdint>

#define D_MODEL 1024
#define NUM_HEADS 16
#define D_K 64
#define BATCH 4
#define SEQ 2048
#define BH (BATCH * NUM_HEADS)          // 64
#define M_ROWS (BATCH * SEQ)            // 8192

// Scratch (device globals; no dynamic allocation allowed)
__device__ float g_q[(size_t)BH * SEQ * D_K];
__device__ float g_k[(size_t)BH * SEQ * D_K];
__device__ float g_vt[(size_t)BH * D_K * SEQ];   // V transposed: [bh][d][s]
__device__ float g_ctx[(size_t)M_ROWS * D_MODEL];
__device__ float g_l[(size_t)BH * SEQ];          // INVERSE softmax row sums
__device__ float g_attn_fb[(size_t)BH * SEQ * SEQ];

// Round fp32 -> tf32 (round-to-nearest; HMMA then truncates losslessly)
__device__ __forceinline__ uint32_t rn_tf32(float x) {
    return (__float_as_uint(x) + 0x1000u) & 0xFFFFE000u;
}

__device__ __forceinline__ void mma_tf32(float* d, const uint32_t* a, const uint32_t* b) {
    asm volatile(
        "mma.sync.aligned.m16n8k8.row.col.f32.tf32.tf32.f32 "
        "{%0,%1,%2,%3}, {%4,%5,%6,%7}, {%8,%9}, {%0,%1,%2,%3};"
        : "+f"(d[0]), "+f"(d[1]), "+f"(d[2]), "+f"(d[3])
        : "r"(a[0]), "r"(a[1]), "r"(a[2]), "r"(a[3]), "r"(b[0]), "r"(b[1]));
}

// Fragment smem block strides (padded to break STS bank conflicts)
#define ABLK 132   // 128 floats + 4 pad
#define BBLK 66    // 64 floats + 2 pad

// ---------------------------------------------------------------------------
// Projection GEMM:  C = A(M x K, K-major) * B(N x K, K-major)^T   (tf32 MMA)
// Block tile 128 x 128, BK = 32, 256 threads, warps 4x2, 2 CTAs/SM.
// EPI: 0 = split-heads Q/K (+bias), 1 = V transposed (+bias), 2 = row-major (+bias)
// ---------------------------------------------------------------------------
template <int EPI>
__global__ void __launch_bounds__(256, 2) mma_gemm(
    const float* __restrict__ A, const float* __restrict__ B,
    const float* __restrict__ bias, float* __restrict__ C,
    int K, int lda, int ldb)
{
    constexpr int A_FLOATS = 32 * ABLK;
    constexpr int B_FLOATS = 64 * BBLK;

    extern __shared__ float smf[];
    float* As = smf;
    float* Bs = smf + 2 * A_FLOATS;

    const int tid = threadIdx.x;
    const int wid = tid >> 5, lid = tid & 31;
    const int warp_m = wid >> 1, warp_n = wid & 1;
    const int bm = blockIdx.y * 128;
    const int bn = blockIdx.x * 128;

    const float* Ab = A + (size_t)bm * lda;
    const float* Bb = B + (size_t)bn * ldb;

    float4 ra[4], rb[4];

    auto ldg_tiles = [&](int k0) {
#pragma unroll
        for (int it = 0; it < 4; it++) {
            int f = tid + it * 256;
            int row = f >> 3, k4 = f & 7;
            ra[it] = *(const float4*)(Ab + (size_t)row * lda + k0 + k4 * 4);
            rb[it] = *(const float4*)(Bb + (size_t)row * ldb + k0 + k4 * 4);
        }
    };

    auto sts_tiles = [&](int buf) {
        float* da = As + buf * A_FLOATS;
        float* db = Bs + buf * B_FLOATS;
#pragma unroll
        for (int it = 0; it < 4; it++) {
            int f = tid + it * 256;
            int row = f >> 3, k4 = f & 7;
            {
                int ma = row >> 4, r = row & 15;
                int ka = k4 >> 1;
                int slot = ((k4 & 1) << 1) | (r >> 3);
                float* p = da + ((ka * 8 + ma) * ABLK + ((r & 7) << 4) + slot);
                p[0]  = __uint_as_float(rn_tf32(ra[it].x));
                p[4]  = __uint_as_float(rn_tf32(ra[it].y));
                p[8]  = __uint_as_float(rn_tf32(ra[it].z));
                p[12] = __uint_as_float(rn_tf32(ra[it].w));
            }
            {
                int na = row >> 3, nn = row & 7;
                int ka = k4 >> 1;
                int slot = k4 & 1;
                float* p = db + ((ka * 16 + na) * BBLK + (nn << 3) + slot);
                p[0] = __uint_as_float(rn_tf32(rb[it].x));
                p[2] = __uint_as_float(rn_tf32(rb[it].y));
                p[4] = __uint_as_float(rn_tf32(rb[it].z));
                p[6] = __uint_as_float(rn_tf32(rb[it].w));
            }
        }
    };

    float acc[2][8][4];
#pragma unroll
    for (int im = 0; im < 2; im++)
#pragma unroll
        for (int in = 0; in < 8; in++)
#pragma unroll
            for (int c = 0; c < 4; c++) acc[im][in][c] = 0.f;

    const int KS = K >> 5;
    ldg_tiles(0);
    sts_tiles(0);
    ldg_tiles(32);
    __syncthreads();

    for (int ks = 0; ks < KS; ks++) {
        if (ks + 1 < KS) sts_tiles((ks + 1) & 1);
        if (ks + 2 < KS) ldg_tiles((ks + 2) << 5);

        const float* Ad = As + (ks & 1) * A_FLOATS;
        const float* Bd = Bs + (ks & 1) * B_FLOATS;
#pragma unroll
        for (int ka = 0; ka < 4; ka++) {
            uint32_t afr[2][4];
#pragma unroll
            for (int im = 0; im < 2; im++) {
                const float4 v = *(const float4*)(Ad + (ka * 8 + warp_m * 2 + im) * ABLK + lid * 4);
                afr[im][0] = __float_as_uint(v.x); afr[im][1] = __float_as_uint(v.y);
                afr[im][2] = __float_as_uint(v.z); afr[im][3] = __float_as_uint(v.w);
            }
            uint32_t bfr[8][2];
#pragma unroll
            for (int in = 0; in < 8; in++) {
                const float2 v = *(const float2*)(Bd + (ka * 16 + warp_n * 8 + in) * BBLK + lid * 2);
                bfr[in][0] = __float_as_uint(v.x); bfr[in][1] = __float_as_uint(v.y);
            }
#pragma unroll
            for (int im = 0; im < 2; im++)
#pragma unroll
                for (int in = 0; in < 8; in++)
                    mma_tf32(acc[im][in], afr[im], bfr[in]);
        }
        __syncthreads();
    }

    const int g = lid >> 2, cq = lid & 3;
#pragma unroll
    for (int im = 0; im < 2; im++) {
        const int mbase = bm + warp_m * 32 + im * 16 + g;
#pragma unroll
        for (int in = 0; in < 8; in++) {
            const int n0 = bn + warp_n * 64 + in * 8 + cq * 2;
            const float c0 = acc[im][in][0], c1 = acc[im][in][1];
            const float c2 = acc[im][in][2], c3 = acc[im][in][3];
            if (EPI == 0) {
                const float2 bv = *(const float2*)(bias + n0);
                const int h = n0 >> 6, d = n0 & 63;
#pragma unroll
                for (int rr = 0; rr < 2; rr++) {
                    const int m = mbase + rr * 8;
                    const int b = m >> 11, s = m & 2047;
                    float2 o; o.x = (rr ? c2 : c0) + bv.x; o.y = (rr ? c3 : c1) + bv.y;
                    *(float2*)&C[(((size_t)(b * NUM_HEADS + h) * SEQ) + s) * D_K + d] = o;
                }
            } else if (EPI == 1) {
                const float b0 = bias[n0], b1 = bias[n0 + 1];
                const int h = n0 >> 6, d = n0 & 63;
#pragma unroll
                for (int rr = 0; rr < 2; rr++) {
                    const int m = mbase + rr * 8;
                    const int b = m >> 11, s = m & 2047;
                    const size_t base = ((size_t)(b * NUM_HEADS + h) * D_K + d) * SEQ + s;
                    C[base]       = (rr ? c2 : c0) + b0;
                    C[base + SEQ] = (rr ? c3 : c1) + b1;
                }
            } else {
                const float2 bv = *(const float2*)(bias + n0);
#pragma unroll
                for (int rr = 0; rr < 2; rr++) {
                    const int m = mbase + rr * 8;
                    float2 o; o.x = (rr ? c2 : c0) + bv.x; o.y = (rr ? c3 : c1) + bv.y;
                    *(float2*)&C[(size_t)m * D_MODEL + n0] = o;
                }
            }
        }
    }
}

// ---------------------------------------------------------------------------
// flashA v5: fused scores + exp + row-sum + ctx, 512 threads, fp32 P smem.
// Scores: warp grid 4m x 4n, warp tile 32x32 (tf32).
// ctx: split-k — warp covers {2 rowblocks} x {4 natoms = 32 d} x {8 katoms};
//      warp_n&1 selects d-half, warp_n>>1 selects kg-half. 2-way merge at end.
// Stores INVERSE row sums to g_l.
// ---------------------------------------------------------------------------
#define FB_Q    0                        // Q frags: 64*ABLK = 8448
#define FB_K0   (64 * ABLK)              // 8448
#define FB_KB   (128 * BBLK)             // 8448 per K buffer
#define FB_P    (FB_K0 + 2 * FB_KB)      // 25344, P frags 128*ABLK = 16896
#define FB_X    FB_P                     // end-of-kernel merge buffer (8*1056)
#define FB_V    (FB_P + 128 * ABLK)      // 42240, V frags 128*BBLK = 8448
#define FB_PART (FB_V + 128 * BBLK)      // 50688 (4 x 128)
#define FB_LSUM (FB_PART + 512)          // 51200
#define FB_TOT  (FB_LSUM + 128)          // 51328 floats = 205312 B

__global__ void __launch_bounds__(512) flash_kernel()
{
    extern __shared__ float smf[];
    const int tid = threadIdx.x;
    const int wid = tid >> 5, lid = tid & 31;
    const int warp_m = wid >> 2, warp_n = wid & 3;   // 4 x 4 warp grid
    const int g = lid >> 2, cq = lid & 3;
    const int bm = blockIdx.x * 128;
    const int bh = blockIdx.y;

    const float* qp = g_q + (size_t)bh * SEQ * D_K + (size_t)bm * D_K;
    const float* kp = g_k + (size_t)bh * SEQ * D_K;
    const float* vp = g_vt + (size_t)bh * D_K * SEQ;

    // ---- stage Q tile into A-frag layout (rows 128 x k 64) ----
#pragma unroll
    for (int it = 0; it < 4; it++) {
        int f = tid + it * 512;
        int row = f >> 4, c4 = f & 15;
        float4 v = *(const float4*)(qp + (size_t)row * D_K + c4 * 4);
        int ma = row >> 4, r = row & 15;
        int ka = c4 >> 1;
        int slot = ((c4 & 1) << 1) | (r >> 3);
        float* p = smf + FB_Q + ((ka * 8 + ma) * ABLK + ((r & 7) << 4) + slot);
        p[0]  = __uint_as_float(rn_tf32(v.x));
        p[4]  = __uint_as_float(rn_tf32(v.y));
        p[8]  = __uint_as_float(rn_tf32(v.z));
        p[12] = __uint_as_float(rn_tf32(v.w));
    }

    float4 rk[4];
    auto ldg_k = [&](int t) {
        const float* kb = kp + (size_t)(t * 128) * D_K;
#pragma unroll
        for (int it = 0; it < 4; it++) {
            int f = tid + it * 512;
            int row = f >> 4, c4 = f & 15;
            rk[it] = *(const float4*)(kb + (size_t)row * D_K + c4 * 4);
        }
    };
    auto sts_k = [&](int buf) {
        float* db = smf + FB_K0 + buf * FB_KB;
#pragma unroll
        for (int it = 0; it < 4; it++) {
            int f = tid + it * 512;
            int row = f >> 4, c4 = f & 15;
            int na = row >> 3, nn = row & 7;
            int ka = c4 >> 1, slot = c4 & 1;
            float* p = db + ((ka * 16 + na) * BBLK + (nn << 3) + slot);
            p[0] = __uint_as_float(rn_tf32(rk[it].x));
            p[2] = __uint_as_float(rn_tf32(rk[it].y));
            p[4] = __uint_as_float(rn_tf32(rk[it].z));
            p[6] = __uint_as_float(rn_tf32(rk[it].w));
        }
    };

    float4 rv[2];
    auto ldg_v = [&](int t, int half) {
        const float* vb = vp + t * 128;
#pragma unroll
        for (int it = 0; it < 2; it++) {
            int f = tid + (half * 2 + it) * 512;
            int row = f >> 5, c4 = f & 31;
            rv[it] = *(const float4*)(vb + (size_t)row * SEQ + c4 * 4);
        }
    };
    auto sts_v = [&](int half) {
#pragma unroll
        for (int it = 0; it < 2; it++) {
            int f = tid + (half * 2 + it) * 512;
            int row = f >> 5, c4 = f & 31;
            int na = row >> 3, nn = row & 7;
            int ka = c4 >> 1, slot = c4 & 1;
            float* p = smf + FB_V + ((ka * 8 + na) * BBLK + (nn << 3) + slot);
            p[0] = __uint_as_float(rn_tf32(rv[it].x));
            p[2] = __uint_as_float(rn_tf32(rv[it].y));
            p[4] = __uint_as_float(rn_tf32(rv[it].z));
            p[6] = __uint_as_float(rn_tf32(rv[it].w));
        }
    };

    // k-partial ctx accumulator: 32 rows x 32 d (d-half selected by warp_n&1,
    // kg-half by warp_n>>1)
    float acc2[2][4][4];
#pragma unroll
    for (int im = 0; im < 2; im++)
#pragma unroll
        for (int in = 0; in < 4; in++)
#pragma unroll
            for (int c = 0; c < 4; c++) acc2[im][in][c] = 0.f;
    float racc[2][2] = {{0.f, 0.f}, {0.f, 0.f}};

    const int dhalf = warp_n & 1;        // 0/1: d columns 0-31 / 32-63
    const int kghalf = (warp_n >> 1) * 8;

    ldg_k(0); sts_k(0); ldg_k(1);
    __syncthreads();

    for (int t = 0; t < 16; t++) {
        if (t + 1 < 16) sts_k((t + 1) & 1);
        if (t + 2 < 16) ldg_k(t + 2);

        // ---- scores MMA: warp tile 32 rows x 32 cols ----
        float acc[2][4][4];
#pragma unroll
        for (int im = 0; im < 2; im++)
#pragma unroll
            for (int in = 0; in < 4; in++)
#pragma unroll
                for (int c = 0; c < 4; c++) acc[im][in][c] = 0.f;

        const float* Kd = smf + FB_K0 + (t & 1) * FB_KB;
#pragma unroll
        for (int ka = 0; ka < 8; ka++) {
            uint32_t afr[2][4];
#pragma unroll
            for (int im = 0; im < 2; im++) {
                const float4 v = *(const float4*)(smf + FB_Q + (ka * 8 + warp_m * 2 + im) * ABLK + lid * 4);
                afr[im][0] = __float_as_uint(v.x); afr[im][1] = __float_as_uint(v.y);
                afr[im][2] = __float_as_uint(v.z); afr[im][3] = __float_as_uint(v.w);
            }
            uint32_t bfr[4][2];
#pragma unroll
            for (int in = 0; in < 4; in++) {
                const float2 v = *(const float2*)(Kd + (ka * 16 + warp_n * 4 + in) * BBLK + lid * 2);
                bfr[in][0] = __float_as_uint(v.x); bfr[in][1] = __float_as_uint(v.y);
            }
#pragma unroll
            for (int im = 0; im < 2; im++)
#pragma unroll
                for (int in = 0; in < 4; in++)
                    mma_tf32(acc[im][in], afr[im], bfr[in]);
        }

        // ---- e = exp(s/8); row sums; float2 scatter to P-frag ----
#pragma unroll
        for (int im = 0; im < 2; im++) {
            ldg_v(t, im);
            const int row_blk = warp_m * 2 + im;           // 16-row block idx
#pragma unroll
            for (int in = 0; in < 4; in++) {
                const int col0 = warp_n * 32 + in * 8 + cq * 2;
#pragma unroll
                for (int j2 = 0; j2 < 2; j2++) {
                    const int col = col0 + j2;
                    const float e0 = __expf(acc[im][in][j2] * 0.125f);
                    const float e1 = __expf(acc[im][in][2 + j2] * 0.125f);
                    racc[im][0] += e0;
                    racc[im][1] += e1;
                    const int kk = col & 7;
                    const int word = ((col >> 3) * 8 + row_blk) * ABLK +
                                     g * 16 + (kk & 3) * 4 + ((kk >> 2) << 1);
                    float2 o; o.x = __uint_as_float(rn_tf32(e0));
                    o.y = __uint_as_float(rn_tf32(e1));
                    *(float2*)(smf + FB_P + word) = o;
                }
            }
            sts_v(im);
        }
        __syncthreads();

        // ---- ctx MMA: 8 kg atoms (half), 32 rows x 32 d (half) ----
#pragma unroll
        for (int kg = 0; kg < 8; kg++) {
            const int kge = kghalf + kg;
            uint32_t afr[2][4];
#pragma unroll
            for (int im = 0; im < 2; im++) {
                const float4 v = *(const float4*)(smf + FB_P + (kge * 8 + warp_m * 2 + im) * ABLK + lid * 4);
                afr[im][0] = __float_as_uint(v.x); afr[im][1] = __float_as_uint(v.y);
                afr[im][2] = __float_as_uint(v.z); afr[im][3] = __float_as_uint(v.w);
            }
#pragma unroll
            for (int in = 0; in < 4; in++) {
                uint32_t bfr[2];
                const float2 v = *(const float2*)(smf + FB_V + (kge * 8 + dhalf * 4 + in) * BBLK + lid * 2);
                bfr[0] = __float_as_uint(v.x); bfr[1] = __float_as_uint(v.y);
#pragma unroll
                for (int im = 0; im < 2; im++)
                    mma_tf32(acc2[im][in], afr[im], bfr);
            }
        }
        __syncthreads();
    }

    // ---- finalize row sums (deterministic reduction), store INVERSE ----
#pragma unroll
    for (int im = 0; im < 2; im++)
#pragma unroll
        for (int rr = 0; rr < 2; rr++) {
            float s = racc[im][rr];
            s += __shfl_xor_sync(0xffffffffu, s, 1);
            s += __shfl_xor_sync(0xffffffffu, s, 2);
            if (cq == 0)
                smf[FB_PART + warp_n * 128 + warp_m * 32 + im * 16 + rr * 8 + g] = s;
        }
    __syncthreads();
    if (tid < 128) {
        float l = smf[FB_PART + tid] + smf[FB_PART + 128 + tid] +
                  smf[FB_PART + 256 + tid] + smf[FB_PART + 384 + tid];
        float inv = 1.f / l;
        smf[FB_LSUM + tid] = inv;
        g_l[(size_t)bh * SEQ + bm + tid] = inv;
    }
    __syncthreads();

    // ---- merge kg-half partials (warp pairs warp_n and warp_n^2) ----
    // warps with kghalf=8 stash their acc2 into smem (stride-33, conflict-free)
    if (warp_n >= 2) {
        float* base = smf + FB_X + (warp_m * 2 + dhalf) * (32 * 33) + lid * 33;
#pragma unroll
        for (int im = 0; im < 2; im++)
#pragma unroll
            for (int in = 0; in < 4; in++)
#pragma unroll
                for (int c = 0; c < 4; c++)
                    base[(im * 4 + in) * 4 + c] = acc2[im][in][c];
    }
    __syncthreads();

    if (warp_n < 2) {
        const int b = bh >> 4, h = bh & 15;
        const float* base = smf + FB_X + (warp_m * 2 + dhalf) * (32 * 33) + lid * 33;
#pragma unroll
        for (int im = 0; im < 2; im++) {
#pragma unroll
            for (int rr = 0; rr < 2; rr++) {
                const int rowl = warp_m * 32 + im * 16 + g + rr * 8;
                const float inv = smf[FB_LSUM + rowl];
                const int srow = bm + rowl;
#pragma unroll
                for (int in = 0; in < 4; in++) {
                    const int n0 = dhalf * 32 + in * 8 + cq * 2;
                    float2 o;
                    o.x = (acc2[im][in][rr ? 2 : 0] + base[(im * 4 + in) * 4 + (rr ? 2 : 0)]) * inv;
                    o.y = (acc2[im][in][rr ? 3 : 1] + base[(im * 4 + in) * 4 + (rr ? 3 : 1)]) * inv;
                    *(float2*)&g_ctx[((size_t)(b * SEQ + srow)) * D_MODEL + h * D_K + n0] = o;
                }
            }
        }
    }
}

// ---------------------------------------------------------------------------
// attnW (512 threads): recompute scores (tf32), write attn = exp(s/8) * inv_l.
// ---------------------------------------------------------------------------
#define AW_Q    0
#define AW_K0   (64 * ABLK)
#define AW_KB   (128 * BBLK)
#define AW_INV  (AW_K0 + 2 * AW_KB)     // 25344
#define AW_TOT  (AW_INV + 128)          // 25472 floats

__global__ void __launch_bounds__(512) attnw_kernel(float* __restrict__ attn)
{
    extern __shared__ float smf[];
    const int tid = threadIdx.x;
    const int wid = tid >> 5, lid = tid & 31;
    const int warp_m = wid >> 2, warp_n = wid & 3;
    const int g = lid >> 2, cq = lid & 3;
    const int bm = blockIdx.x * 128;
    const int bh = blockIdx.y;

    const float* qp = g_q + (size_t)bh * SEQ * D_K + (size_t)bm * D_K;
    const float* kp = g_k + (size_t)bh * SEQ * D_K;
    float* ap = attn + (size_t)bh * SEQ * SEQ;

    if (tid < 128)
        smf[AW_INV + tid] = g_l[(size_t)bh * SEQ + bm + tid];   // already inverse

#pragma unroll
    for (int it = 0; it < 4; it++) {
        int f = tid + it * 512;
        int row = f >> 4, c4 = f & 15;
        float4 v = *(const float4*)(qp + (size_t)row * D_K + c4 * 4);
        int ma = row >> 4, r = row & 15;
        int ka = c4 >> 1;
        int slot = ((c4 & 1) << 1) | (r >> 3);
        float* p = smf + AW_Q + ((ka * 8 + ma) * ABLK + ((r & 7) << 4) + slot);
        p[0]  = __uint_as_float(rn_tf32(v.x));
        p[4]  = __uint_as_float(rn_tf32(v.y));
        p[8]  = __uint_as_float(rn_tf32(v.z));
        p[12] = __uint_as_float(rn_tf32(v.w));
    }

    float4 rk[4];
    auto ldg_k = [&](int t) {
        const float* kb = kp + (size_t)(t * 128) * D_K;
#pragma unroll
        for (int it = 0; it < 4; it++) {
            int f = tid + it * 512;
            int row = f >> 4, c4 = f & 15;
            rk[it] = *(const float4*)(kb + (size_t)row * D_K + c4 * 4);
        }
    };
    auto sts_k = [&](int buf) {
        float* db = smf + AW_K0 + buf * AW_KB;
#pragma unroll
        for (int it = 0; it < 4; it++) {
            int f = tid + it * 512;
            int row = f >> 4, c4 = f & 15;
            int na = row >> 3, nn = row & 7;
            int ka = c4 >> 1, slot = c4 & 1;
            float* p = db + ((ka * 16 + na) * BBLK + (nn << 3) + slot);
            p[0] = __uint_as_float(rn_tf32(rk[it].x));
            p[2] = __uint_as_float(rn_tf32(rk[it].y));
            p[4] = __uint_as_float(rn_tf32(rk[it].z));
            p[6] = __uint_as_float(rn_tf32(rk[it].w));
        }
    };

    ldg_k(0); sts_k(0); ldg_k(1);
    __syncthreads();

    const int row0q = warp_m * 32 + g;
    const float iv0 = smf[AW_INV + row0q];
    const float iv1 = smf[AW_INV + row0q + 8];
    const float iv2 = smf[AW_INV + row0q + 16];
    const float iv3 = smf[AW_INV + row0q + 24];

    for (int t = 0; t < 16; t++) {
        if (t + 1 < 16) sts_k((t + 1) & 1);
        if (t + 2 < 16) ldg_k(t + 2);

        float acc[2][4][4];
#pragma unroll
        for (int im = 0; im < 2; im++)
#pragma unroll
            for (int in = 0; in < 4; in++)
#pragma unroll
                for (int c = 0; c < 4; c++) acc[im][in][c] = 0.f;

        const float* Kd = smf + AW_K0 + (t & 1) * AW_KB;
#pragma unroll
        for (int ka = 0; ka < 8; ka++) {
            uint32_t afr[2][4];
#pragma unroll
            for (int im = 0; im < 2; im++) {
                const float4 v = *(const float4*)(smf + AW_Q + (ka * 8 + warp_m * 2 + im) * ABLK + lid * 4);
                afr[im][0] = __float_as_uint(v.x); afr[im][1] = __float_as_uint(v.y);
                afr[im][2] = __float_as_uint(v.z); afr[im][3] = __float_as_uint(v.w);
            }
            uint32_t bfr[4][2];
#pragma unroll
            for (int in = 0; in < 4; in++) {
                const float2 v = *(const float2*)(Kd + (ka * 16 + warp_n * 4 + in) * BBLK + lid * 2);
                bfr[in][0] = __float_as_uint(v.x); bfr[in][1] = __float_as_uint(v.y);
            }
#pragma unroll
            for (int im = 0; im < 2; im++)
#pragma unroll
                for (int in = 0; in < 4; in++)
                    mma_tf32(acc[im][in], afr[im], bfr[in]);
        }

#pragma unroll
        for (int im = 0; im < 2; im++) {
            const int mrow = bm + warp_m * 32 + im * 16 + g;
            const float a0 = im ? iv2 : iv0;
            const float a1 = im ? iv3 : iv1;
#pragma unroll
            for (int in = 0; in < 4; in++) {
                const int col = t * 128 + warp_n * 32 + in * 8 + cq * 2;
                float2 o0, o1;
                o0.x = __expf(acc[im][in][0] * 0.125f) * a0;
                o0.y = __expf(acc[im][in][1] * 0.125f) * a0;
                o1.x = __expf(acc[im][in][2] * 0.125f) * a1;
                o1.y = __expf(acc[im][in][3] * 0.125f) * a1;
                __stcs((float2*)&ap[(size_t)mrow * SEQ + col], o0);
                __stcs((float2*)&ap[(size_t)(mrow + 8) * SEQ + col], o1);
            }
        }
        __syncthreads();
    }
}

extern "C" void kernel_launch(void* const* d_in, const int* in_sizes, int n_in,
                              void* d_out, int out_size) {
    const float* Q  = (const float*)d_in[0];
    const float* K  = (const float*)d_in[1];
    const float* V  = (const float*)d_in[2];
    const float* Wq = (const float*)d_in[3];
    const float* bq = (const float*)d_in[4];
    const float* Wk = (const float*)d_in[5];
    const float* bk = (const float*)d_in[6];
    const float* Wv = (const float*)d_in[7];
    const float* bv = (const float*)d_in[8];
    const float* Wo = (const float*)d_in[9];
    const float* bo = (const float*)d_in[10];

    float* out = (float*)d_out;

    const size_t OUT_ELEMS  = (size_t)M_ROWS * D_MODEL;
    const size_t ATTN_ELEMS = (size_t)BH * SEQ * SEQ;

    float* attn;
    if ((size_t)out_size >= OUT_ELEMS + ATTN_ELEMS) {
        attn = out + OUT_ELEMS;
    } else {
        void* p = nullptr;
        cudaGetSymbolAddress(&p, g_attn_fb);
        attn = (float*)p;
    }

    float *qp, *kp, *vtp, *cp;
    { void* t; cudaGetSymbolAddress(&t, g_q);   qp  = (float*)t; }
    { void* t; cudaGetSymbolAddress(&t, g_k);   kp  = (float*)t; }
    { void* t; cudaGetSymbolAddress(&t, g_vt);  vtp = (float*)t; }
    { void* t; cudaGetSymbolAddress(&t, g_ctx); cp  = (float*)t; }

    const int SMP  = (2 * 32 * ABLK + 2 * 64 * BBLK) * 4;
    const int SMFA = FB_TOT * 4;
    const int SMAW = AW_TOT * 4;

    cudaFuncSetAttribute(mma_gemm<0>, cudaFuncAttributeMaxDynamicSharedMemorySize, SMP);
    cudaFuncSetAttribute(mma_gemm<1>, cudaFuncAttributeMaxDynamicSharedMemorySize, SMP);
    cudaFuncSetAttribute(mma_gemm<2>, cudaFuncAttributeMaxDynamicSharedMemorySize, SMP);
    cudaFuncSetAttribute(flash_kernel, cudaFuncAttributeMaxDynamicSharedMemorySize, SMFA);
    cudaFuncSetAttribute(attnw_kernel, cudaFuncAttributeMaxDynamicSharedMemorySize, SMAW);

    dim3 projGrid(D_MODEL / 128, M_ROWS / 128);     // (8, 64)
    mma_gemm<0><<<projGrid, 256, SMP>>>(Q, Wq, bq, qp, 1024, 1024, 1024);
    mma_gemm<0><<<projGrid, 256, SMP>>>(K, Wk, bk, kp, 1024, 1024, 1024);
    mma_gemm<1><<<projGrid, 256, SMP>>>(V, Wv, bv, vtp, 1024, 1024, 1024);

    dim3 attGrid(SEQ / 128, BH);                    // (16, 64)
    flash_kernel<<<attGrid, 512, SMFA>>>();
    attnw_kernel<<<attGrid, 512, SMAW>>>(attn);

    mma_gemm<2><<<projGrid, 256, SMP>>>(cp, Wo, bo, out, 1024, 1024, 1024);
}

// round 13
// speedup vs baseline: 1.2131x; 1.0207x over previous
#include <cuda_runtime.h>
#include <cstdint>

#define D_MODEL 1024
#define NUM_HEADS 16
#define D_K 64
#define BATCH 4
#define SEQ 2048
#define BH (BATCH * NUM_HEADS)          // 64
#define M_ROWS (BATCH * SEQ)            // 8192

// Scratch (device globals; no dynamic allocation allowed)
__device__ float g_q[(size_t)BH * SEQ * D_K];
__device__ float g_k[(size_t)BH * SEQ * D_K];
__device__ float g_vt[(size_t)BH * D_K * SEQ];   // V transposed: [bh][d][s]
__device__ float g_ctx[(size_t)M_ROWS * D_MODEL];
__device__ float g_l[(size_t)BH * SEQ];          // INVERSE softmax row sums
__device__ float g_attn_fb[(size_t)BH * SEQ * SEQ];

// Round fp32 -> tf32 (round-to-nearest; HMMA then truncates losslessly)
__device__ __forceinline__ uint32_t rn_tf32(float x) {
    return (__float_as_uint(x) + 0x1000u) & 0xFFFFE000u;
}

__device__ __forceinline__ void mma_tf32(float* d, const uint32_t* a, const uint32_t* b) {
    asm volatile(
        "mma.sync.aligned.m16n8k8.row.col.f32.tf32.tf32.f32 "
        "{%0,%1,%2,%3}, {%4,%5,%6,%7}, {%8,%9}, {%0,%1,%2,%3};"
        : "+f"(d[0]), "+f"(d[1]), "+f"(d[2]), "+f"(d[3])
        : "r"(a[0]), "r"(a[1]), "r"(a[2]), "r"(a[3]), "r"(b[0]), "r"(b[1]));
}

// Fragment smem block strides (padded to break STS bank conflicts)
#define ABLK 132   // 128 floats + 4 pad
#define BBLK 66    // 64 floats + 2 pad

// ---------------------------------------------------------------------------
// Projection GEMM:  C = A(M x K, K-major) * B(N x K, K-major)^T   (tf32 MMA)
// Block tile 128 x 128, BK = 32, 256 threads, warps 4x2, 2 CTAs/SM.
// EPI: 0 = split-heads Q/K (+bias), 1 = V transposed (+bias), 2 = row-major (+bias)
// ---------------------------------------------------------------------------
template <int EPI>
__global__ void __launch_bounds__(256, 2) mma_gemm(
    const float* __restrict__ A, const float* __restrict__ B,
    const float* __restrict__ bias, float* __restrict__ C,
    int K, int lda, int ldb)
{
    constexpr int A_FLOATS = 32 * ABLK;
    constexpr int B_FLOATS = 64 * BBLK;

    extern __shared__ float smf[];
    float* As = smf;
    float* Bs = smf + 2 * A_FLOATS;

    const int tid = threadIdx.x;
    const int wid = tid >> 5, lid = tid & 31;
    const int warp_m = wid >> 1, warp_n = wid & 1;
    const int bm = blockIdx.y * 128;
    const int bn = blockIdx.x * 128;

    const float* Ab = A + (size_t)bm * lda;
    const float* Bb = B + (size_t)bn * ldb;

    float4 ra[4], rb[4];

    auto ldg_tiles = [&](int k0) {
#pragma unroll
        for (int it = 0; it < 4; it++) {
            int f = tid + it * 256;
            int row = f >> 3, k4 = f & 7;
            ra[it] = *(const float4*)(Ab + (size_t)row * lda + k0 + k4 * 4);
            rb[it] = *(const float4*)(Bb + (size_t)row * ldb + k0 + k4 * 4);
        }
    };

    auto sts_tiles = [&](int buf) {
        float* da = As + buf * A_FLOATS;
        float* db = Bs + buf * B_FLOATS;
#pragma unroll
        for (int it = 0; it < 4; it++) {
            int f = tid + it * 256;
            int row = f >> 3, k4 = f & 7;
            {
                int ma = row >> 4, r = row & 15;
                int ka = k4 >> 1;
                int slot = ((k4 & 1) << 1) | (r >> 3);
                float* p = da + ((ka * 8 + ma) * ABLK + ((r & 7) << 4) + slot);
                p[0]  = __uint_as_float(rn_tf32(ra[it].x));
                p[4]  = __uint_as_float(rn_tf32(ra[it].y));
                p[8]  = __uint_as_float(rn_tf32(ra[it].z));
                p[12] = __uint_as_float(rn_tf32(ra[it].w));
            }
            {
                int na = row >> 3, nn = row & 7;
                int ka = k4 >> 1;
                int slot = k4 & 1;
                float* p = db + ((ka * 16 + na) * BBLK + (nn << 3) + slot);
                p[0] = __uint_as_float(rn_tf32(rb[it].x));
                p[2] = __uint_as_float(rn_tf32(rb[it].y));
                p[4] = __uint_as_float(rn_tf32(rb[it].z));
                p[6] = __uint_as_float(rn_tf32(rb[it].w));
            }
        }
    };

    float acc[2][8][4];
#pragma unroll
    for (int im = 0; im < 2; im++)
#pragma unroll
        for (int in = 0; in < 8; in++)
#pragma unroll
            for (int c = 0; c < 4; c++) acc[im][in][c] = 0.f;

    const int KS = K >> 5;
    ldg_tiles(0);
    sts_tiles(0);
    ldg_tiles(32);
    __syncthreads();

    for (int ks = 0; ks < KS; ks++) {
        if (ks + 1 < KS) sts_tiles((ks + 1) & 1);
        if (ks + 2 < KS) ldg_tiles((ks + 2) << 5);

        const float* Ad = As + (ks & 1) * A_FLOATS;
        const float* Bd = Bs + (ks & 1) * B_FLOATS;
#pragma unroll
        for (int ka = 0; ka < 4; ka++) {
            uint32_t afr[2][4];
#pragma unroll
            for (int im = 0; im < 2; im++) {
                const float4 v = *(const float4*)(Ad + (ka * 8 + warp_m * 2 + im) * ABLK + lid * 4);
                afr[im][0] = __float_as_uint(v.x); afr[im][1] = __float_as_uint(v.y);
                afr[im][2] = __float_as_uint(v.z); afr[im][3] = __float_as_uint(v.w);
            }
            uint32_t bfr[8][2];
#pragma unroll
            for (int in = 0; in < 8; in++) {
                const float2 v = *(const float2*)(Bd + (ka * 16 + warp_n * 8 + in) * BBLK + lid * 2);
                bfr[in][0] = __float_as_uint(v.x); bfr[in][1] = __float_as_uint(v.y);
            }
#pragma unroll
            for (int im = 0; im < 2; im++)
#pragma unroll
                for (int in = 0; in < 8; in++)
                    mma_tf32(acc[im][in], afr[im], bfr[in]);
        }
        __syncthreads();
    }

    const int g = lid >> 2, cq = lid & 3;
#pragma unroll
    for (int im = 0; im < 2; im++) {
        const int mbase = bm + warp_m * 32 + im * 16 + g;
#pragma unroll
        for (int in = 0; in < 8; in++) {
            const int n0 = bn + warp_n * 64 + in * 8 + cq * 2;
            const float c0 = acc[im][in][0], c1 = acc[im][in][1];
            const float c2 = acc[im][in][2], c3 = acc[im][in][3];
            if (EPI == 0) {
                const float2 bv = *(const float2*)(bias + n0);
                const int h = n0 >> 6, d = n0 & 63;
#pragma unroll
                for (int rr = 0; rr < 2; rr++) {
                    const int m = mbase + rr * 8;
                    const int b = m >> 11, s = m & 2047;
                    float2 o; o.x = (rr ? c2 : c0) + bv.x; o.y = (rr ? c3 : c1) + bv.y;
                    *(float2*)&C[(((size_t)(b * NUM_HEADS + h) * SEQ) + s) * D_K + d] = o;
                }
            } else if (EPI == 1) {
                const float b0 = bias[n0], b1 = bias[n0 + 1];
                const int h = n0 >> 6, d = n0 & 63;
#pragma unroll
                for (int rr = 0; rr < 2; rr++) {
                    const int m = mbase + rr * 8;
                    const int b = m >> 11, s = m & 2047;
                    const size_t base = ((size_t)(b * NUM_HEADS + h) * D_K + d) * SEQ + s;
                    C[base]       = (rr ? c2 : c0) + b0;
                    C[base + SEQ] = (rr ? c3 : c1) + b1;
                }
            } else {
                const float2 bv = *(const float2*)(bias + n0);
#pragma unroll
                for (int rr = 0; rr < 2; rr++) {
                    const int m = mbase + rr * 8;
                    float2 o; o.x = (rr ? c2 : c0) + bv.x; o.y = (rr ? c3 : c1) + bv.y;
                    *(float2*)&C[(size_t)m * D_MODEL + n0] = o;
                }
            }
        }
    }
}

// ---------------------------------------------------------------------------
// flashA v5: fused scores + exp + row-sum + ctx, 512 threads, fp32 P smem.
// (identical to round-12 passing version)
// ---------------------------------------------------------------------------
#define FB_Q    0                        // Q frags: 64*ABLK = 8448
#define FB_K0   (64 * ABLK)              // 8448
#define FB_KB   (128 * BBLK)             // 8448 per K buffer
#define FB_P    (FB_K0 + 2 * FB_KB)      // 25344, P frags 128*ABLK = 16896
#define FB_X    FB_P                     // end-of-kernel merge buffer (8*1056)
#define FB_V    (FB_P + 128 * ABLK)      // 42240, V frags 128*BBLK = 8448
#define FB_PART (FB_V + 128 * BBLK)      // 50688 (4 x 128)
#define FB_LSUM (FB_PART + 512)          // 51200
#define FB_TOT  (FB_LSUM + 128)          // 51328 floats = 205312 B

__global__ void __launch_bounds__(512) flash_kernel()
{
    extern __shared__ float smf[];
    const int tid = threadIdx.x;
    const int wid = tid >> 5, lid = tid & 31;
    const int warp_m = wid >> 2, warp_n = wid & 3;   // 4 x 4 warp grid
    const int g = lid >> 2, cq = lid & 3;
    const int bm = blockIdx.x * 128;
    const int bh = blockIdx.y;

    const float* qp = g_q + (size_t)bh * SEQ * D_K + (size_t)bm * D_K;
    const float* kp = g_k + (size_t)bh * SEQ * D_K;
    const float* vp = g_vt + (size_t)bh * D_K * SEQ;

    // ---- stage Q tile into A-frag layout (rows 128 x k 64) ----
#pragma unroll
    for (int it = 0; it < 4; it++) {
        int f = tid + it * 512;
        int row = f >> 4, c4 = f & 15;
        float4 v = *(const float4*)(qp + (size_t)row * D_K + c4 * 4);
        int ma = row >> 4, r = row & 15;
        int ka = c4 >> 1;
        int slot = ((c4 & 1) << 1) | (r >> 3);
        float* p = smf + FB_Q + ((ka * 8 + ma) * ABLK + ((r & 7) << 4) + slot);
        p[0]  = __uint_as_float(rn_tf32(v.x));
        p[4]  = __uint_as_float(rn_tf32(v.y));
        p[8]  = __uint_as_float(rn_tf32(v.z));
        p[12] = __uint_as_float(rn_tf32(v.w));
    }

    float4 rk[4];
    auto ldg_k = [&](int t) {
        const float* kb = kp + (size_t)(t * 128) * D_K;
#pragma unroll
        for (int it = 0; it < 4; it++) {
            int f = tid + it * 512;
            int row = f >> 4, c4 = f & 15;
            rk[it] = *(const float4*)(kb + (size_t)row * D_K + c4 * 4);
        }
    };
    auto sts_k = [&](int buf) {
        float* db = smf + FB_K0 + buf * FB_KB;
#pragma unroll
        for (int it = 0; it < 4; it++) {
            int f = tid + it * 512;
            int row = f >> 4, c4 = f & 15;
            int na = row >> 3, nn = row & 7;
            int ka = c4 >> 1, slot = c4 & 1;
            float* p = db + ((ka * 16 + na) * BBLK + (nn << 3) + slot);
            p[0] = __uint_as_float(rn_tf32(rk[it].x));
            p[2] = __uint_as_float(rn_tf32(rk[it].y));
            p[4] = __uint_as_float(rn_tf32(rk[it].z));
            p[6] = __uint_as_float(rn_tf32(rk[it].w));
        }
    };

    float4 rv[2];
    auto ldg_v = [&](int t, int half) {
        const float* vb = vp + t * 128;
#pragma unroll
        for (int it = 0; it < 2; it++) {
            int f = tid + (half * 2 + it) * 512;
            int row = f >> 5, c4 = f & 31;
            rv[it] = *(const float4*)(vb + (size_t)row * SEQ + c4 * 4);
        }
    };
    auto sts_v = [&](int half) {
#pragma unroll
        for (int it = 0; it < 2; it++) {
            int f = tid + (half * 2 + it) * 512;
            int row = f >> 5, c4 = f & 31;
            int na = row >> 3, nn = row & 7;
            int ka = c4 >> 1, slot = c4 & 1;
            float* p = smf + FB_V + ((ka * 8 + na) * BBLK + (nn << 3) + slot);
            p[0] = __uint_as_float(rn_tf32(rv[it].x));
            p[2] = __uint_as_float(rn_tf32(rv[it].y));
            p[4] = __uint_as_float(rn_tf32(rv[it].z));
            p[6] = __uint_as_float(rn_tf32(rv[it].w));
        }
    };

    float acc2[2][4][4];
#pragma unroll
    for (int im = 0; im < 2; im++)
#pragma unroll
        for (int in = 0; in < 4; in++)
#pragma unroll
            for (int c = 0; c < 4; c++) acc2[im][in][c] = 0.f;
    float racc[2][2] = {{0.f, 0.f}, {0.f, 0.f}};

    const int dhalf = warp_n & 1;        // 0/1: d columns 0-31 / 32-63
    const int kghalf = (warp_n >> 1) * 8;

    ldg_k(0); sts_k(0); ldg_k(1);
    __syncthreads();

    for (int t = 0; t < 16; t++) {
        if (t + 1 < 16) sts_k((t + 1) & 1);
        if (t + 2 < 16) ldg_k(t + 2);

        // ---- scores MMA: warp tile 32 rows x 32 cols ----
        float acc[2][4][4];
#pragma unroll
        for (int im = 0; im < 2; im++)
#pragma unroll
            for (int in = 0; in < 4; in++)
#pragma unroll
                for (int c = 0; c < 4; c++) acc[im][in][c] = 0.f;

        const float* Kd = smf + FB_K0 + (t & 1) * FB_KB;
#pragma unroll
        for (int ka = 0; ka < 8; ka++) {
            uint32_t afr[2][4];
#pragma unroll
            for (int im = 0; im < 2; im++) {
                const float4 v = *(const float4*)(smf + FB_Q + (ka * 8 + warp_m * 2 + im) * ABLK + lid * 4);
                afr[im][0] = __float_as_uint(v.x); afr[im][1] = __float_as_uint(v.y);
                afr[im][2] = __float_as_uint(v.z); afr[im][3] = __float_as_uint(v.w);
            }
            uint32_t bfr[4][2];
#pragma unroll
            for (int in = 0; in < 4; in++) {
                const float2 v = *(const float2*)(Kd + (ka * 16 + warp_n * 4 + in) * BBLK + lid * 2);
                bfr[in][0] = __float_as_uint(v.x); bfr[in][1] = __float_as_uint(v.y);
            }
#pragma unroll
            for (int im = 0; im < 2; im++)
#pragma unroll
                for (int in = 0; in < 4; in++)
                    mma_tf32(acc[im][in], afr[im], bfr[in]);
        }

        // ---- e = exp(s/8); row sums; float2 scatter to P-frag ----
#pragma unroll
        for (int im = 0; im < 2; im++) {
            ldg_v(t, im);
            const int row_blk = warp_m * 2 + im;           // 16-row block idx
#pragma unroll
            for (int in = 0; in < 4; in++) {
                const int col0 = warp_n * 32 + in * 8 + cq * 2;
#pragma unroll
                for (int j2 = 0; j2 < 2; j2++) {
                    const int col = col0 + j2;
                    const float e0 = __expf(acc[im][in][j2] * 0.125f);
                    const float e1 = __expf(acc[im][in][2 + j2] * 0.125f);
                    racc[im][0] += e0;
                    racc[im][1] += e1;
                    const int kk = col & 7;
                    const int word = ((col >> 3) * 8 + row_blk) * ABLK +
                                     g * 16 + (kk & 3) * 4 + ((kk >> 2) << 1);
                    float2 o; o.x = __uint_as_float(rn_tf32(e0));
                    o.y = __uint_as_float(rn_tf32(e1));
                    *(float2*)(smf + FB_P + word) = o;
                }
            }
            sts_v(im);
        }
        __syncthreads();

        // ---- ctx MMA: 8 kg atoms (half), 32 rows x 32 d (half) ----
#pragma unroll
        for (int kg = 0; kg < 8; kg++) {
            const int kge = kghalf + kg;
            uint32_t afr[2][4];
#pragma unroll
            for (int im = 0; im < 2; im++) {
                const float4 v = *(const float4*)(smf + FB_P + (kge * 8 + warp_m * 2 + im) * ABLK + lid * 4);
                afr[im][0] = __float_as_uint(v.x); afr[im][1] = __float_as_uint(v.y);
                afr[im][2] = __float_as_uint(v.z); afr[im][3] = __float_as_uint(v.w);
            }
#pragma unroll
            for (int in = 0; in < 4; in++) {
                uint32_t bfr[2];
                const float2 v = *(const float2*)(smf + FB_V + (kge * 8 + dhalf * 4 + in) * BBLK + lid * 2);
                bfr[0] = __float_as_uint(v.x); bfr[1] = __float_as_uint(v.y);
#pragma unroll
                for (int im = 0; im < 2; im++)
                    mma_tf32(acc2[im][in], afr[im], bfr);
            }
        }
        __syncthreads();
    }

    // ---- finalize row sums (deterministic reduction), store INVERSE ----
#pragma unroll
    for (int im = 0; im < 2; im++)
#pragma unroll
        for (int rr = 0; rr < 2; rr++) {
            float s = racc[im][rr];
            s += __shfl_xor_sync(0xffffffffu, s, 1);
            s += __shfl_xor_sync(0xffffffffu, s, 2);
            if (cq == 0)
                smf[FB_PART + warp_n * 128 + warp_m * 32 + im * 16 + rr * 8 + g] = s;
        }
    __syncthreads();
    if (tid < 128) {
        float l = smf[FB_PART + tid] + smf[FB_PART + 128 + tid] +
                  smf[FB_PART + 256 + tid] + smf[FB_PART + 384 + tid];
        float inv = 1.f / l;
        smf[FB_LSUM + tid] = inv;
        g_l[(size_t)bh * SEQ + bm + tid] = inv;
    }
    __syncthreads();

    // ---- merge kg-half partials (warp pairs warp_n and warp_n^2) ----
    if (warp_n >= 2) {
        float* base = smf + FB_X + (warp_m * 2 + dhalf) * (32 * 33) + lid * 33;
#pragma unroll
        for (int im = 0; im < 2; im++)
#pragma unroll
            for (int in = 0; in < 4; in++)
#pragma unroll
                for (int c = 0; c < 4; c++)
                    base[(im * 4 + in) * 4 + c] = acc2[im][in][c];
    }
    __syncthreads();

    if (warp_n < 2) {
        const int b = bh >> 4, h = bh & 15;
        const float* base = smf + FB_X + (warp_m * 2 + dhalf) * (32 * 33) + lid * 33;
#pragma unroll
        for (int im = 0; im < 2; im++) {
#pragma unroll
            for (int rr = 0; rr < 2; rr++) {
                const int rowl = warp_m * 32 + im * 16 + g + rr * 8;
                const float inv = smf[FB_LSUM + rowl];
                const int srow = bm + rowl;
#pragma unroll
                for (int in = 0; in < 4; in++) {
                    const int n0 = dhalf * 32 + in * 8 + cq * 2;
                    float2 o;
                    o.x = (acc2[im][in][rr ? 2 : 0] + base[(im * 4 + in) * 4 + (rr ? 2 : 0)]) * inv;
                    o.y = (acc2[im][in][rr ? 3 : 1] + base[(im * 4 + in) * 4 + (rr ? 3 : 1)]) * inv;
                    *(float2*)&g_ctx[((size_t)(b * SEQ + srow)) * D_MODEL + h * D_K + n0] = o;
                }
            }
        }
    }
}

// ---------------------------------------------------------------------------
// attnW (512 threads): recompute scores (tf32), write attn = exp(s/8) * inv_l.
// ---------------------------------------------------------------------------
#define AW_Q    0
#define AW_K0   (64 * ABLK)
#define AW_KB   (128 * BBLK)
#define AW_INV  (AW_K0 + 2 * AW_KB)     // 25344
#define AW_TOT  (AW_INV + 128)          // 25472 floats

__global__ void __launch_bounds__(512) attnw_kernel(float* __restrict__ attn)
{
    extern __shared__ float smf[];
    const int tid = threadIdx.x;
    const int wid = tid >> 5, lid = tid & 31;
    const int warp_m = wid >> 2, warp_n = wid & 3;
    const int g = lid >> 2, cq = lid & 3;
    const int bm = blockIdx.x * 128;
    const int bh = blockIdx.y;

    const float* qp = g_q + (size_t)bh * SEQ * D_K + (size_t)bm * D_K;
    const float* kp = g_k + (size_t)bh * SEQ * D_K;
    float* ap = attn + (size_t)bh * SEQ * SEQ;

    if (tid < 128)
        smf[AW_INV + tid] = g_l[(size_t)bh * SEQ + bm + tid];   // already inverse

#pragma unroll
    for (int it = 0; it < 4; it++) {
        int f = tid + it * 512;
        int row = f >> 4, c4 = f & 15;
        float4 v = *(const float4*)(qp + (size_t)row * D_K + c4 * 4);
        int ma = row >> 4, r = row & 15;
        int ka = c4 >> 1;
        int slot = ((c4 & 1) << 1) | (r >> 3);
        float* p = smf + AW_Q + ((ka * 8 + ma) * ABLK + ((r & 7) << 4) + slot);
        p[0]  = __uint_as_float(rn_tf32(v.x));
        p[4]  = __uint_as_float(rn_tf32(v.y));
        p[8]  = __uint_as_float(rn_tf32(v.z));
        p[12] = __uint_as_float(rn_tf32(v.w));
    }

    float4 rk[4];
    auto ldg_k = [&](int t) {
        const float* kb = kp + (size_t)(t * 128) * D_K;
#pragma unroll
        for (int it = 0; it < 4; it++) {
            int f = tid + it * 512;
            int row = f >> 4, c4 = f & 15;
            rk[it] = *(const float4*)(kb + (size_t)row * D_K + c4 * 4);
        }
    };
    auto sts_k = [&](int buf) {
        float* db = smf + AW_K0 + buf * AW_KB;
#pragma unroll
        for (int it = 0; it < 4; it++) {
            int f = tid + it * 512;
            int row = f >> 4, c4 = f & 15;
            int na = row >> 3, nn = row & 7;
            int ka = c4 >> 1, slot = c4 & 1;
            float* p = db + ((ka * 16 + na) * BBLK + (nn << 3) + slot);
            p[0] = __uint_as_float(rn_tf32(rk[it].x));
            p[2] = __uint_as_float(rn_tf32(rk[it].y));
            p[4] = __uint_as_float(rn_tf32(rk[it].z));
            p[6] = __uint_as_float(rn_tf32(rk[it].w));
        }
    };

    ldg_k(0); sts_k(0); ldg_k(1);
    __syncthreads();

    const int row0q = warp_m * 32 + g;
    const float iv0 = smf[AW_INV + row0q];
    const float iv1 = smf[AW_INV + row0q + 8];
    const float iv2 = smf[AW_INV + row0q + 16];
    const float iv3 = smf[AW_INV + row0q + 24];

    for (int t = 0; t < 16; t++) {
        if (t + 1 < 16) sts_k((t + 1) & 1);
        if (t + 2 < 16) ldg_k(t + 2);

        float acc[2][4][4];
#pragma unroll
        for (int im = 0; im < 2; im++)
#pragma unroll
            for (int in = 0; in < 4; in++)
#pragma unroll
                for (int c = 0; c < 4; c++) acc[im][in][c] = 0.f;

        const float* Kd = smf + AW_K0 + (t & 1) * AW_KB;
#pragma unroll
        for (int ka = 0; ka < 8; ka++) {
            uint32_t afr[2][4];
#pragma unroll
            for (int im = 0; im < 2; im++) {
                const float4 v = *(const float4*)(smf + AW_Q + (ka * 8 + warp_m * 2 + im) * ABLK + lid * 4);
                afr[im][0] = __float_as_uint(v.x); afr[im][1] = __float_as_uint(v.y);
                afr[im][2] = __float_as_uint(v.z); afr[im][3] = __float_as_uint(v.w);
            }
            uint32_t bfr[4][2];
#pragma unroll
            for (int in = 0; in < 4; in++) {
                const float2 v = *(const float2*)(Kd + (ka * 16 + warp_n * 4 + in) * BBLK + lid * 2);
                bfr[in][0] = __float_as_uint(v.x); bfr[in][1] = __float_as_uint(v.y);
            }
#pragma unroll
            for (int im = 0; im < 2; im++)
#pragma unroll
                for (int in = 0; in < 4; in++)
                    mma_tf32(acc[im][in], afr[im], bfr[in]);
        }

#pragma unroll
        for (int im = 0; im < 2; im++) {
            const int mrow = bm + warp_m * 32 + im * 16 + g;
            const float a0 = im ? iv2 : iv0;
            const float a1 = im ? iv3 : iv1;
#pragma unroll
            for (int in = 0; in < 4; in++) {
                const int col = t * 128 + warp_n * 32 + in * 8 + cq * 2;
                float2 o0, o1;
                o0.x = __expf(acc[im][in][0] * 0.125f) * a0;
                o0.y = __expf(acc[im][in][1] * 0.125f) * a0;
                o1.x = __expf(acc[im][in][2] * 0.125f) * a1;
                o1.y = __expf(acc[im][in][3] * 0.125f) * a1;
                __stcs((float2*)&ap[(size_t)mrow * SEQ + col], o0);
                __stcs((float2*)&ap[(size_t)(mrow + 8) * SEQ + col], o1);
            }
        }
        __syncthreads();
    }
}

extern "C" void kernel_launch(void* const* d_in, const int* in_sizes, int n_in,
                              void* d_out, int out_size) {
    const float* Q  = (const float*)d_in[0];
    const float* K  = (const float*)d_in[1];
    const float* V  = (const float*)d_in[2];
    const float* Wq = (const float*)d_in[3];
    const float* bq = (const float*)d_in[4];
    const float* Wk = (const float*)d_in[5];
    const float* bk = (const float*)d_in[6];
    const float* Wv = (const float*)d_in[7];
    const float* bv = (const float*)d_in[8];
    const float* Wo = (const float*)d_in[9];
    const float* bo = (const float*)d_in[10];

    float* out = (float*)d_out;

    const size_t OUT_ELEMS  = (size_t)M_ROWS * D_MODEL;
    const size_t ATTN_ELEMS = (size_t)BH * SEQ * SEQ;

    float* attn;
    if ((size_t)out_size >= OUT_ELEMS + ATTN_ELEMS) {
        attn = out + OUT_ELEMS;
    } else {
        void* p = nullptr;
        cudaGetSymbolAddress(&p, g_attn_fb);
        attn = (float*)p;
    }

    float *qp, *kp, *vtp, *cp;
    { void* t; cudaGetSymbolAddress(&t, g_q);   qp  = (float*)t; }
    { void* t; cudaGetSymbolAddress(&t, g_k);   kp  = (float*)t; }
    { void* t; cudaGetSymbolAddress(&t, g_vt);  vtp = (float*)t; }
    { void* t; cudaGetSymbolAddress(&t, g_ctx); cp  = (float*)t; }

    const int SMP  = (2 * 32 * ABLK + 2 * 64 * BBLK) * 4;
    const int SMFA = FB_TOT * 4;
    const int SMAW = AW_TOT * 4;

    cudaFuncSetAttribute(mma_gemm<0>, cudaFuncAttributeMaxDynamicSharedMemorySize, SMP);
    cudaFuncSetAttribute(mma_gemm<1>, cudaFuncAttributeMaxDynamicSharedMemorySize, SMP);
    cudaFuncSetAttribute(mma_gemm<2>, cudaFuncAttributeMaxDynamicSharedMemorySize, SMP);
    cudaFuncSetAttribute(flash_kernel, cudaFuncAttributeMaxDynamicSharedMemorySize, SMFA);
    cudaFuncSetAttribute(attnw_kernel, cudaFuncAttributeMaxDynamicSharedMemorySize, SMAW);

    // Persistent secondary streams + fork/join events (created once, on the
    // uncaptured correctness call; reused identically on every call so the
    // captured work is deterministic).
    static cudaStream_t sB = nullptr, sC = nullptr;
    static cudaEvent_t evRoot = nullptr, evB = nullptr, evC = nullptr,
                       evF = nullptr, evA = nullptr;
    if (sB == nullptr) {
        cudaStreamCreateWithFlags(&sB, cudaStreamNonBlocking);
        cudaStreamCreateWithFlags(&sC, cudaStreamNonBlocking);
        cudaEventCreateWithFlags(&evRoot, cudaEventDisableTiming);
        cudaEventCreateWithFlags(&evB, cudaEventDisableTiming);
        cudaEventCreateWithFlags(&evC, cudaEventDisableTiming);
        cudaEventCreateWithFlags(&evF, cudaEventDisableTiming);
        cudaEventCreateWithFlags(&evA, cudaEventDisableTiming);
    }
    const cudaStream_t s0 = (cudaStream_t)0;

    dim3 projGrid(D_MODEL / 128, M_ROWS / 128);     // (8, 64)
    dim3 attGrid(SEQ / 128, BH);                    // (16, 64)

    // Fork: Q on main stream, K on sB, V on sC (independent projections)
    cudaEventRecord(evRoot, s0);
    cudaStreamWaitEvent(sB, evRoot, 0);
    cudaStreamWaitEvent(sC, evRoot, 0);

    mma_gemm<0><<<projGrid, 256, SMP, s0>>>(Q, Wq, bq, qp, 1024, 1024, 1024);
    mma_gemm<0><<<projGrid, 256, SMP, sB>>>(K, Wk, bk, kp, 1024, 1024, 1024);
    mma_gemm<1><<<projGrid, 256, SMP, sC>>>(V, Wv, bv, vtp, 1024, 1024, 1024);

    cudaEventRecord(evB, sB);
    cudaEventRecord(evC, sC);
    cudaStreamWaitEvent(s0, evB, 0);
    cudaStreamWaitEvent(s0, evC, 0);

    // flash needs all of q, k, vt
    flash_kernel<<<attGrid, 512, SMFA, s0>>>();

    // Fork: attnw (needs g_l, q, k) runs concurrently with out projection
    // (needs g_ctx) — both depend only on flash.
    cudaEventRecord(evF, s0);
    cudaStreamWaitEvent(sB, evF, 0);
    attnw_kernel<<<attGrid, 512, SMAW, sB>>>(attn);
    cudaEventRecord(evA, sB);

    mma_gemm<2><<<projGrid, 256, SMP, s0>>>(cp, Wo, bo, out, 1024, 1024, 1024);

    // Join before graph end
    cudaStreamWaitEvent(s0, evA, 0);
}